// round 13
// baseline (speedup 1.0000x reference)
#include <cuda_runtime.h>
#include <cuda_fp16.h>
#include <cstdint>

#define NMAX 100000
#define EMAX 1600000
#define FIN  128
#define FOUT 40
#define SCAN_BLK 1024

typedef unsigned long long ull;

// Scratch (static __device__ — no allocations allowed)
__device__ int    g_is64;
__device__ int    g_src32 [EMAX];
__device__ int    g_dst32 [EMAX];
__device__ int    g_csr   [EMAX];        // src ids grouped by dst
__device__ int    g_degi  [NMAX];
__device__ int    g_fill  [NMAX];
__device__ int    g_rowptr[NMAX + 1];
__device__ int    g_bsum  [(NMAX + SCAN_BLK - 1) / SCAN_BLK];
__device__ int    g_boff  [(NMAX + SCAN_BLK - 1) / SCAN_BLK];
__device__ float  g_dinv[NMAX];
__device__ __half g_hh  [(size_t)NMAX * FIN];   // x @ W1 (unscaled, fp16)
__device__ float  g_a1  [(size_t)NMAX * FIN];   // relu(layer-1 out), fp32
__device__ __half g_h2h [(size_t)NMAX * FOUT];  // dinv * (a1 @ W2), fp16

// ---------------------------------------------------------------------------
// preproc
// ---------------------------------------------------------------------------
__global__ void k_zero_cnt(int n) {
    int i = blockIdx.x * blockDim.x + threadIdx.x;
    if (i < n) { g_degi[i] = 0; g_fill[i] = 0; }
    if (i == 0) g_is64 = 1;
}

__global__ void k_detect(const long long* __restrict__ ei, int n, int count) {
    int i = blockIdx.x * blockDim.x + threadIdx.x;
    if (i < count) {
        long long v = ei[i];
        if (v < 0 || v >= (long long)n) atomicAnd(&g_is64, 0);
    }
}

__global__ void k_convert_hist(const void* __restrict__ ei, int E) {
    int e = blockIdx.x * blockDim.x + threadIdx.x;
    if (e >= E) return;
    int s, d;
    if (g_is64) {
        const long long* p = (const long long*)ei;
        s = (int)p[e];
        d = (int)p[E + e];
    } else {
        const int* p = (const int*)ei;
        s = p[e];
        d = p[E + e];
    }
    g_src32[e] = s;
    g_dst32[e] = d;
    atomicAdd(&g_degi[d], 1);
}

__global__ void k_scanA(int n) {
    __shared__ int sh[SCAN_BLK];
    int tid = threadIdx.x;
    int i = blockIdx.x * SCAN_BLK + tid;
    int v = (i < n) ? g_degi[i] : 0;
    if (i < n) g_dinv[i] = rsqrtf((float)v + 1.0f);  // +1 = self loop
    sh[tid] = v;
    __syncthreads();
    for (int off = 1; off < SCAN_BLK; off <<= 1) {
        int t = (tid >= off) ? sh[tid - off] : 0;
        __syncthreads();
        sh[tid] += t;
        __syncthreads();
    }
    if (i < n) g_rowptr[i] = sh[tid] - v;  // exclusive within block
    if (tid == SCAN_BLK - 1) g_bsum[blockIdx.x] = sh[tid];
}

__global__ void k_scanB(int nblocks, int n, int E) {
    __shared__ int sh[256];
    int tid = threadIdx.x;
    int carry = 0;
    for (int base = 0; base < nblocks; base += 256) {
        int i = base + tid;
        int v = (i < nblocks) ? g_bsum[i] : 0;
        sh[tid] = v;
        __syncthreads();
        for (int off = 1; off < 256; off <<= 1) {
            int t = (tid >= off) ? sh[tid - off] : 0;
            __syncthreads();
            sh[tid] += t;
            __syncthreads();
        }
        if (i < nblocks) g_boff[i] = carry + sh[tid] - v;
        __syncthreads();
        carry += sh[255];
        __syncthreads();
    }
    if (tid == 0) g_rowptr[n] = E;
}

__global__ void k_scanC(int n) {
    int i = blockIdx.x * blockDim.x + threadIdx.x;
    if (i < n) g_rowptr[i] += g_boff[i / SCAN_BLK];
}

__global__ void k_fill(int E) {
    int e = blockIdx.x * blockDim.x + threadIdx.x;
    if (e >= E) return;
    int d = g_dst32[e];
    int pos = g_rowptr[d] + atomicAdd(&g_fill[d], 1);
    g_csr[pos] = g_src32[e];
}

// ---------------------------------------------------------------------------
// GEMM1: h = x @ W1 (unscaled), packed f32x2 FMA, fp16 output.
// block = 256 threads, tile = 128 rows x 128 cols, K chunked by 16.
// thread: cg = t&7 -> cols cg*16..+15 ; rg = t>>3 -> rows rg*4..+3.
// Ws cells [kk][j][cg] (8 consecutive cells per j -> 1 wf, 4-lane bcast).
// Xs cells [row][kk2 ^ ((rg&3)<<1)] -> bank-disjoint 1 wf.
// Per warp/kk2: 12 LDS wf vs 64 FFMA2 -> fma-bound.
// ---------------------------------------------------------------------------
__global__ void __launch_bounds__(256, 2)
k_gemm1(const float* __restrict__ x, const float* __restrict__ W, int n) {
    const int KC  = 16;
    const int KC2 = KC / 2;
    __shared__ float      Ws [KC * FIN];     // 8 KB, [kk][j][cg] 16B cells
    __shared__ ulonglong2 Xs2[128 * KC2];    // 16 KB, [row][cell swizzled]

    int t    = threadIdx.x;
    int cg   = t & 7;          // col group: cols cg*16 .. cg*16+15
    int rg   = t >> 3;         // row group: rows rg*4 .. rg*4+3
    int row0 = blockIdx.x * 128;
    int sx   = (rg & 3) << 1;  // Xs bank swizzle for this thread

    ull acc[4][8];
#pragma unroll
    for (int r = 0; r < 4; r++)
#pragma unroll
        for (int c = 0; c < 8; c++) acc[r][c] = 0ull;

    for (int kc = 0; kc < FIN; kc += KC) {
        // stage W: float4 f -> kk = f>>5, c4 = f&31; cell = kk*32+(c4&3)*8+(c4>>2)
        for (int f = t; f < KC * FIN / 4; f += 256) {
            float4 v = ((const float4*)(W + (size_t)kc * FIN))[f];
            int kk = f >> 5;
            int c4 = f & 31;
            ((float4*)Ws)[kk * 32 + (c4 & 3) * 8 + (c4 >> 2)] = v;
        }
        // stage x: [row][k2 ^ swz] cells = {dup(v_2k), dup(v_2k+1)}
        for (int i = t; i < 128 * KC2; i += 256) {
            int r  = i >> 3;
            int k2 = i & 7;
            int gr = row0 + r;
            float2 v = make_float2(0.f, 0.f);
            if (gr < n) v = *(const float2*)(x + (size_t)gr * FIN + kc + k2 * 2);
            ulonglong2 e;
            *(float2*)&e.x = make_float2(v.x, v.x);
            *(float2*)&e.y = make_float2(v.y, v.y);
            Xs2[r * KC2 + (k2 ^ (((r >> 2) & 3) << 1))] = e;
        }
        __syncthreads();

#pragma unroll
        for (int kk2 = 0; kk2 < KC2; kk2++) {
            int kidx = kk2 ^ sx;
            ulonglong2 xx[4];
#pragma unroll
            for (int r = 0; r < 4; r++)
                xx[r] = Xs2[(rg * 4 + r) * KC2 + kidx];
#pragma unroll
            for (int half = 0; half < 2; half++) {
                int kk = 2 * kk2 + half;
                const ulonglong2* wrow = (const ulonglong2*)(Ws + kk * FIN);
                ulonglong2 w0 = wrow[0 * 8 + cg];
                ulonglong2 w1 = wrow[1 * 8 + cg];
                ulonglong2 w2 = wrow[2 * 8 + cg];
                ulonglong2 w3 = wrow[3 * 8 + cg];
#pragma unroll
                for (int r = 0; r < 4; r++) {
                    ull xv = half ? xx[r].y : xx[r].x;
                    asm("fma.rn.f32x2 %0, %1, %2, %0;" : "+l"(acc[r][0]) : "l"(xv), "l"(w0.x));
                    asm("fma.rn.f32x2 %0, %1, %2, %0;" : "+l"(acc[r][1]) : "l"(xv), "l"(w0.y));
                    asm("fma.rn.f32x2 %0, %1, %2, %0;" : "+l"(acc[r][2]) : "l"(xv), "l"(w1.x));
                    asm("fma.rn.f32x2 %0, %1, %2, %0;" : "+l"(acc[r][3]) : "l"(xv), "l"(w1.y));
                    asm("fma.rn.f32x2 %0, %1, %2, %0;" : "+l"(acc[r][4]) : "l"(xv), "l"(w2.x));
                    asm("fma.rn.f32x2 %0, %1, %2, %0;" : "+l"(acc[r][5]) : "l"(xv), "l"(w2.y));
                    asm("fma.rn.f32x2 %0, %1, %2, %0;" : "+l"(acc[r][6]) : "l"(xv), "l"(w3.x));
                    asm("fma.rn.f32x2 %0, %1, %2, %0;" : "+l"(acc[r][7]) : "l"(xv), "l"(w3.y));
                }
            }
        }
        __syncthreads();
    }

#pragma unroll
    for (int r = 0; r < 4; r++) {
        int gr = row0 + rg * 4 + r;
        if (gr < n) {
            __half* op = g_hh + (size_t)gr * FIN + cg * 16;
            uint4 st0, st1;
            {
                __half2 h0 = __float22half2_rn(*(float2*)&acc[r][0]);
                __half2 h1 = __float22half2_rn(*(float2*)&acc[r][1]);
                __half2 h2 = __float22half2_rn(*(float2*)&acc[r][2]);
                __half2 h3 = __float22half2_rn(*(float2*)&acc[r][3]);
                st0.x = *(unsigned*)&h0; st0.y = *(unsigned*)&h1;
                st0.z = *(unsigned*)&h2; st0.w = *(unsigned*)&h3;
            }
            {
                __half2 h0 = __float22half2_rn(*(float2*)&acc[r][4]);
                __half2 h1 = __float22half2_rn(*(float2*)&acc[r][5]);
                __half2 h2 = __float22half2_rn(*(float2*)&acc[r][6]);
                __half2 h3 = __float22half2_rn(*(float2*)&acc[r][7]);
                st1.x = *(unsigned*)&h0; st1.y = *(unsigned*)&h1;
                st1.z = *(unsigned*)&h2; st1.w = *(unsigned*)&h3;
            }
            ((uint4*)op)[0] = st0;
            ((uint4*)op)[1] = st1;
        }
    }
}

// ---------------------------------------------------------------------------
// agg1 (pull): a1[d] = relu( di * (sum_s dinv[s]*h[s] + di*h[d]) + b1 )
// warp per node, lane holds 4 cols (one uint2 = 4 halves), fp16 gathers
// ---------------------------------------------------------------------------
__device__ __forceinline__ float4 ld_h4(const __half* p, int lane) {
    uint2 u = *((const uint2*)p + lane);
    float2 lo = __half22float2(*(__half2*)&u.x);
    float2 hi = __half22float2(*(__half2*)&u.y);
    return make_float4(lo.x, lo.y, hi.x, hi.y);
}

__global__ void k_agg1(const float* __restrict__ b1, int n) {
    int node = blockIdx.x * 8 + (threadIdx.x >> 5);
    int lane = threadIdx.x & 31;
    if (node >= n) return;

    float di = g_dinv[node];
    float4 sv = ld_h4(g_hh + (size_t)node * FIN, lane);
    float4 acc = make_float4(sv.x * di, sv.y * di, sv.z * di, sv.w * di);

    int beg = g_rowptr[node], end = g_rowptr[node + 1];
    int k = beg;
    for (; k + 3 < end; k += 4) {
        int s0 = g_csr[k],     s1 = g_csr[k + 1];
        int s2 = g_csr[k + 2], s3 = g_csr[k + 3];
        float w0 = g_dinv[s0], w1 = g_dinv[s1];
        float w2 = g_dinv[s2], w3 = g_dinv[s3];
        float4 v0 = ld_h4(g_hh + (size_t)s0 * FIN, lane);
        float4 v1 = ld_h4(g_hh + (size_t)s1 * FIN, lane);
        float4 v2 = ld_h4(g_hh + (size_t)s2 * FIN, lane);
        float4 v3 = ld_h4(g_hh + (size_t)s3 * FIN, lane);
        acc.x = fmaf(v0.x, w0, fmaf(v1.x, w1, fmaf(v2.x, w2, fmaf(v3.x, w3, acc.x))));
        acc.y = fmaf(v0.y, w0, fmaf(v1.y, w1, fmaf(v2.y, w2, fmaf(v3.y, w3, acc.y))));
        acc.z = fmaf(v0.z, w0, fmaf(v1.z, w1, fmaf(v2.z, w2, fmaf(v3.z, w3, acc.z))));
        acc.w = fmaf(v0.w, w0, fmaf(v1.w, w1, fmaf(v2.w, w2, fmaf(v3.w, w3, acc.w))));
    }
    for (; k < end; k++) {
        int s = g_csr[k];
        float w = g_dinv[s];
        float4 v = ld_h4(g_hh + (size_t)s * FIN, lane);
        acc.x = fmaf(v.x, w, acc.x);
        acc.y = fmaf(v.y, w, acc.y);
        acc.z = fmaf(v.z, w, acc.z);
        acc.w = fmaf(v.w, w, acc.w);
    }

    float4 bb = ((const float4*)b1)[lane];
    float4 z;
    z.x = fmaxf(fmaf(acc.x, di, bb.x), 0.f);
    z.y = fmaxf(fmaf(acc.y, di, bb.y), 0.f);
    z.z = fmaxf(fmaf(acc.z, di, bb.z), 0.f);
    z.w = fmaxf(fmaf(acc.w, di, bb.w), 0.f);
    ((float4*)(g_a1 + (size_t)node * FIN))[lane] = z;
}

// ---------------------------------------------------------------------------
// GEMM2: h2 = dinv * (a1 @ W2), register-tiled; epilogue stores fp16
// ---------------------------------------------------------------------------
__global__ void k_gemm2(const float* __restrict__ W2, int n) {
    const int KC = 32;
    __shared__ float W2s[FIN * FOUT];        // 20 KB
    __shared__ float As[128 * 36];           // 18 KB (pad 36)

    int t    = threadIdx.x;
    int r    = t >> 1;
    int half = t & 1;
    int row0 = blockIdx.x * 128;

    for (int i = t; i < FIN * FOUT / 4; i += 256)
        ((float4*)W2s)[i] = ((const float4*)W2)[i];

    float4 acc[5];
#pragma unroll
    for (int j = 0; j < 5; j++) acc[j] = make_float4(0.f, 0.f, 0.f, 0.f);

    for (int kc = 0; kc < FIN; kc += KC) {
        for (int i = t; i < 128 * (KC / 4); i += 256) {
            int rr = i >> 3;
            int k4 = i & 7;
            int gr = row0 + rr;
            float4 v = make_float4(0.f, 0.f, 0.f, 0.f);
            if (gr < n) v = ((const float4*)(g_a1 + (size_t)gr * FIN + kc))[k4];
            *(float4*)&As[rr * 36 + k4 * 4] = v;
        }
        __syncthreads();

#pragma unroll 4
        for (int kk = 0; kk < KC; kk++) {
            float av = As[r * 36 + kk];
            const float4* wp = (const float4*)(W2s + (kc + kk) * FOUT + half * 20);
            float4 w0 = wp[0];
            float4 w1 = wp[1];
            float4 w2 = wp[2];
            float4 w3 = wp[3];
            float4 w4 = wp[4];
            acc[0].x = fmaf(av, w0.x, acc[0].x); acc[0].y = fmaf(av, w0.y, acc[0].y);
            acc[0].z = fmaf(av, w0.z, acc[0].z); acc[0].w = fmaf(av, w0.w, acc[0].w);
            acc[1].x = fmaf(av, w1.x, acc[1].x); acc[1].y = fmaf(av, w1.y, acc[1].y);
            acc[1].z = fmaf(av, w1.z, acc[1].z); acc[1].w = fmaf(av, w1.w, acc[1].w);
            acc[2].x = fmaf(av, w2.x, acc[2].x); acc[2].y = fmaf(av, w2.y, acc[2].y);
            acc[2].z = fmaf(av, w2.z, acc[2].z); acc[2].w = fmaf(av, w2.w, acc[2].w);
            acc[3].x = fmaf(av, w3.x, acc[3].x); acc[3].y = fmaf(av, w3.y, acc[3].y);
            acc[3].z = fmaf(av, w3.z, acc[3].z); acc[3].w = fmaf(av, w3.w, acc[3].w);
            acc[4].x = fmaf(av, w4.x, acc[4].x); acc[4].y = fmaf(av, w4.y, acc[4].y);
            acc[4].z = fmaf(av, w4.z, acc[4].z); acc[4].w = fmaf(av, w4.w, acc[4].w);
        }
        __syncthreads();
    }

    int gr = row0 + r;
    if (gr < n) {
        float di = g_dinv[gr];
#pragma unroll
        for (int j = 0; j < 5; j++) {
            float4 o = acc[j];
            __half2 lo = __floats2half2_rn(o.x * di, o.y * di);
            __half2 hi = __floats2half2_rn(o.z * di, o.w * di);
            uint2 st;
            st.x = *(unsigned*)&lo;
            st.y = *(unsigned*)&hi;
            *(uint2*)(g_h2h + (size_t)gr * FOUT + half * 20 + j * 4) = st;
        }
    }
}

// ---------------------------------------------------------------------------
// agg2 (pull): out[d] = di * (sum h2[s] + h2[d]) + b2    [h2 pre-scaled fp16]
// warp per node; lanes 0..19 each handle cols 2*lane, 2*lane+1 (half2 loads)
// ---------------------------------------------------------------------------
__global__ void k_agg2(float* __restrict__ out, const float* __restrict__ b2,
                       int n) {
    int node = blockIdx.x * 8 + (threadIdx.x >> 5);
    int lane = threadIdx.x & 31;
    if (node >= n || lane >= 20) return;

    float di = g_dinv[node];
    unsigned u0 = *((const unsigned*)(g_h2h + (size_t)node * FOUT) + lane);
    float2 sv = __half22float2(*(__half2*)&u0);
    float a0 = sv.x, a1 = sv.y;

    int beg = g_rowptr[node], end = g_rowptr[node + 1];
    int k = beg;
    for (; k + 3 < end; k += 4) {
        unsigned v0 = *((const unsigned*)(g_h2h + (size_t)g_csr[k]     * FOUT) + lane);
        unsigned v1 = *((const unsigned*)(g_h2h + (size_t)g_csr[k + 1] * FOUT) + lane);
        unsigned v2 = *((const unsigned*)(g_h2h + (size_t)g_csr[k + 2] * FOUT) + lane);
        unsigned v3 = *((const unsigned*)(g_h2h + (size_t)g_csr[k + 3] * FOUT) + lane);
        float2 f0 = __half22float2(*(__half2*)&v0);
        float2 f1 = __half22float2(*(__half2*)&v1);
        float2 f2 = __half22float2(*(__half2*)&v2);
        float2 f3 = __half22float2(*(__half2*)&v3);
        a0 += (f0.x + f1.x) + (f2.x + f3.x);
        a1 += (f0.y + f1.y) + (f2.y + f3.y);
    }
    for (; k < end; k++) {
        unsigned v = *((const unsigned*)(g_h2h + (size_t)g_csr[k] * FOUT) + lane);
        float2 f = __half22float2(*(__half2*)&v);
        a0 += f.x;
        a1 += f.y;
    }

    float* op = out + (size_t)node * FOUT + 2 * lane;
    op[0] = fmaf(a0, di, b2[2 * lane]);
    op[1] = fmaf(a1, di, b2[2 * lane + 1]);
}

// ---------------------------------------------------------------------------
extern "C" void kernel_launch(void* const* d_in, const int* in_sizes, int n_in,
                              void* d_out, int out_size) {
    const float* x   = (const float*)d_in[0];
    const void*  ei  = d_in[1];
    const float* W1  = (const float*)d_in[2];
    const float* b1  = (const float*)d_in[3];
    const float* W2  = (const float*)d_in[4];
    const float* b2  = (const float*)d_in[5];
    float*       out = (float*)d_out;

    int n = in_sizes[0] / FIN;
    if (n > NMAX) n = NMAX;
    int E = in_sizes[1] / 2;
    if (E > EMAX) E = EMAX;

    int detect_cnt = 2048;
    if (detect_cnt > E) detect_cnt = E;
    int nsb = (n + SCAN_BLK - 1) / SCAN_BLK;

    k_zero_cnt    <<<(n + 255) / 256, 256>>>(n);                 // 1 (also inits g_is64)
    k_detect      <<<(detect_cnt + 255) / 256, 256>>>((const long long*)ei, n, detect_cnt); // 2
    k_convert_hist<<<(E + 255) / 256, 256>>>(ei, E);             // 3
    k_gemm1       <<<(n + 127) / 128, 256>>>(x, W1, n);          // 4 <- profiled
    k_scanA       <<<nsb, SCAN_BLK>>>(n);                        // 5
    k_scanB       <<<1, 256>>>(nsb, n, E);                       // 6
    k_scanC       <<<(n + 255) / 256, 256>>>(n);                 // 7
    k_fill        <<<(E + 255) / 256, 256>>>(E);                 // 8
    k_agg1        <<<(n + 7) / 8, 256>>>(b1, n);                 // 9
    k_gemm2       <<<(n + 127) / 128, 256>>>(W2, n);             // 10
    k_agg2        <<<(n + 7) / 8, 256>>>(out, b2, n);            // 11
}

// round 14
// speedup vs baseline: 1.0972x; 1.0972x over previous
#include <cuda_runtime.h>
#include <cuda_fp16.h>
#include <cstdint>

#define NMAX 100000
#define EMAX 1600000
#define FIN  128
#define FOUT 40
#define SCAN_BLK 1024

typedef unsigned long long ull;

// Scratch (static __device__ — no allocations allowed)
__device__ int    g_is64;
__device__ int    g_src32 [EMAX];
__device__ int    g_dst32 [EMAX];
__device__ int    g_csr   [EMAX];        // src ids grouped by dst
__device__ int    g_degi  [NMAX];
__device__ int    g_fill  [NMAX];
__device__ int    g_rowptr[NMAX + 1];
__device__ int    g_bsum  [(NMAX + SCAN_BLK - 1) / SCAN_BLK];
__device__ int    g_boff  [(NMAX + SCAN_BLK - 1) / SCAN_BLK];
__device__ float  g_dinv[NMAX];
__device__ __half g_hh  [(size_t)NMAX * FIN];   // x @ W1 (unscaled, fp16)
__device__ __half g_a1h [(size_t)NMAX * FIN];   // relu(layer-1 out), fp16
__device__ __half g_h2h [(size_t)NMAX * FOUT];  // dinv * (a1 @ W2), fp16

// ---------------------------------------------------------------------------
// preproc
// ---------------------------------------------------------------------------
__global__ void k_zero_cnt(int n) {
    int i = blockIdx.x * blockDim.x + threadIdx.x;
    if (i < n) { g_degi[i] = 0; g_fill[i] = 0; }
    if (i == 0) g_is64 = 1;
}

__global__ void k_detect(const long long* __restrict__ ei, int n, int count) {
    int i = blockIdx.x * blockDim.x + threadIdx.x;
    if (i < count) {
        long long v = ei[i];
        if (v < 0 || v >= (long long)n) atomicAnd(&g_is64, 0);
    }
}

__global__ void k_convert_hist(const void* __restrict__ ei, int E) {
    int e = blockIdx.x * blockDim.x + threadIdx.x;
    if (e >= E) return;
    int s, d;
    if (g_is64) {
        const long long* p = (const long long*)ei;
        s = (int)p[e];
        d = (int)p[E + e];
    } else {
        const int* p = (const int*)ei;
        s = p[e];
        d = p[E + e];
    }
    g_src32[e] = s;
    g_dst32[e] = d;
    atomicAdd(&g_degi[d], 1);
}

__global__ void k_scanA(int n) {
    __shared__ int sh[SCAN_BLK];
    int tid = threadIdx.x;
    int i = blockIdx.x * SCAN_BLK + tid;
    int v = (i < n) ? g_degi[i] : 0;
    if (i < n) g_dinv[i] = rsqrtf((float)v + 1.0f);  // +1 = self loop
    sh[tid] = v;
    __syncthreads();
    for (int off = 1; off < SCAN_BLK; off <<= 1) {
        int t = (tid >= off) ? sh[tid - off] : 0;
        __syncthreads();
        sh[tid] += t;
        __syncthreads();
    }
    if (i < n) g_rowptr[i] = sh[tid] - v;  // exclusive within block
    if (tid == SCAN_BLK - 1) g_bsum[blockIdx.x] = sh[tid];
}

__global__ void k_scanB(int nblocks, int n, int E) {
    __shared__ int sh[256];
    int tid = threadIdx.x;
    int carry = 0;
    for (int base = 0; base < nblocks; base += 256) {
        int i = base + tid;
        int v = (i < nblocks) ? g_bsum[i] : 0;
        sh[tid] = v;
        __syncthreads();
        for (int off = 1; off < 256; off <<= 1) {
            int t = (tid >= off) ? sh[tid - off] : 0;
            __syncthreads();
            sh[tid] += t;
            __syncthreads();
        }
        if (i < nblocks) g_boff[i] = carry + sh[tid] - v;
        __syncthreads();
        carry += sh[255];
        __syncthreads();
    }
    if (tid == 0) g_rowptr[n] = E;
}

__global__ void k_scanC(int n) {
    int i = blockIdx.x * blockDim.x + threadIdx.x;
    if (i < n) g_rowptr[i] += g_boff[i / SCAN_BLK];
}

__global__ void k_fill(int E) {
    int e = blockIdx.x * blockDim.x + threadIdx.x;
    if (e >= E) return;
    int d = g_dst32[e];
    int pos = g_rowptr[d] + atomicAdd(&g_fill[d], 1);
    g_csr[pos] = g_src32[e];
}

// ---------------------------------------------------------------------------
// GEMM1: h = x @ W1 (unscaled), packed f32x2 FMA, conflict-free smem.
// EXACT R12 configuration (measured 98 us) — do not modify.
// ---------------------------------------------------------------------------
__global__ void __launch_bounds__(256, 2)
k_gemm1(const float* __restrict__ x, const float* __restrict__ W, int n) {
    const int KC  = 32;
    const int KC2 = KC / 2;
    __shared__ float      Ws [KC * FIN];     // 16 KB, [kk][half][cg] 16B cells
    __shared__ ulonglong2 Xs2[128 * KC2];    // 32 KB, [row][kk2 swizzled]

    int t    = threadIdx.x;
    int cg   = t & 15;         // col group: cols cg*8 .. cg*8+7
    int rg   = t >> 4;         // row group: rows rg*8 .. rg*8+7
    int row0 = blockIdx.x * 128;
    int sx   = (rg & 1) << 2;  // Xs bank swizzle for this thread

    ull acc[8][4];
#pragma unroll
    for (int r = 0; r < 8; r++)
#pragma unroll
        for (int c = 0; c < 4; c++) acc[r][c] = 0ull;

    for (int kc = 0; kc < FIN; kc += KC) {
        for (int f = t; f < KC * FIN / 4; f += 256) {
            float4 v = ((const float4*)(W + (size_t)kc * FIN))[f];
            int kk = f >> 5;
            int c4 = f & 31;
            ((float4*)Ws)[kk * 32 + (c4 & 1) * 16 + (c4 >> 1)] = v;
        }
        for (int i = t; i < 128 * KC2; i += 256) {
            int r  = i >> 4;
            int k2 = i & 15;
            int gr = row0 + r;
            float2 v = make_float2(0.f, 0.f);
            if (gr < n) v = *(const float2*)(x + (size_t)gr * FIN + kc + k2 * 2);
            ulonglong2 e;
            *(float2*)&e.x = make_float2(v.x, v.x);
            *(float2*)&e.y = make_float2(v.y, v.y);
            Xs2[r * KC2 + (k2 ^ (((r >> 3) & 1) << 2))] = e;
        }
        __syncthreads();

#pragma unroll 4
        for (int kk2 = 0; kk2 < KC2; kk2++) {
            int kidx = kk2 ^ sx;
#pragma unroll
            for (int half = 0; half < 2; half++) {
                int kk = 2 * kk2 + half;
                ulonglong2 wa = ((const ulonglong2*)Ws)[kk * 32 + cg];
                ulonglong2 wb = ((const ulonglong2*)Ws)[kk * 32 + 16 + cg];
#pragma unroll
                for (int r = 0; r < 8; r++) {
                    ulonglong2 xx = Xs2[(rg * 8 + r) * KC2 + kidx];
                    ull xv = half ? xx.y : xx.x;
                    asm("fma.rn.f32x2 %0, %1, %2, %0;" : "+l"(acc[r][0]) : "l"(xv), "l"(wa.x));
                    asm("fma.rn.f32x2 %0, %1, %2, %0;" : "+l"(acc[r][1]) : "l"(xv), "l"(wa.y));
                    asm("fma.rn.f32x2 %0, %1, %2, %0;" : "+l"(acc[r][2]) : "l"(xv), "l"(wb.x));
                    asm("fma.rn.f32x2 %0, %1, %2, %0;" : "+l"(acc[r][3]) : "l"(xv), "l"(wb.y));
                }
            }
        }
        __syncthreads();
    }

#pragma unroll
    for (int r = 0; r < 8; r++) {
        int gr = row0 + rg * 8 + r;
        if (gr < n) {
            __half2 h0 = __float22half2_rn(*(float2*)&acc[r][0]);
            __half2 h1 = __float22half2_rn(*(float2*)&acc[r][1]);
            __half2 h2 = __float22half2_rn(*(float2*)&acc[r][2]);
            __half2 h3 = __float22half2_rn(*(float2*)&acc[r][3]);
            uint4 st;
            st.x = *(unsigned*)&h0; st.y = *(unsigned*)&h1;
            st.z = *(unsigned*)&h2; st.w = *(unsigned*)&h3;
            *(uint4*)(g_hh + (size_t)gr * FIN + cg * 8) = st;
        }
    }
}

// ---------------------------------------------------------------------------
// agg1 (pull): a1[d] = relu( di * (sum_s dinv[s]*h[s] + di*h[d]) + b1 )
// warp per node, lane holds 4 cols; fp16 gathers, fp16 store
// ---------------------------------------------------------------------------
__device__ __forceinline__ float4 ld_h4(const __half* p, int lane) {
    uint2 u = *((const uint2*)p + lane);
    float2 lo = __half22float2(*(__half2*)&u.x);
    float2 hi = __half22float2(*(__half2*)&u.y);
    return make_float4(lo.x, lo.y, hi.x, hi.y);
}

__global__ void k_agg1(const float* __restrict__ b1, int n) {
    int node = blockIdx.x * 8 + (threadIdx.x >> 5);
    int lane = threadIdx.x & 31;
    if (node >= n) return;

    float di = g_dinv[node];
    float4 sv = ld_h4(g_hh + (size_t)node * FIN, lane);
    float4 acc = make_float4(sv.x * di, sv.y * di, sv.z * di, sv.w * di);

    int beg = g_rowptr[node], end = g_rowptr[node + 1];
    int k = beg;
    for (; k + 3 < end; k += 4) {
        int s0 = g_csr[k],     s1 = g_csr[k + 1];
        int s2 = g_csr[k + 2], s3 = g_csr[k + 3];
        float w0 = g_dinv[s0], w1 = g_dinv[s1];
        float w2 = g_dinv[s2], w3 = g_dinv[s3];
        float4 v0 = ld_h4(g_hh + (size_t)s0 * FIN, lane);
        float4 v1 = ld_h4(g_hh + (size_t)s1 * FIN, lane);
        float4 v2 = ld_h4(g_hh + (size_t)s2 * FIN, lane);
        float4 v3 = ld_h4(g_hh + (size_t)s3 * FIN, lane);
        acc.x = fmaf(v0.x, w0, fmaf(v1.x, w1, fmaf(v2.x, w2, fmaf(v3.x, w3, acc.x))));
        acc.y = fmaf(v0.y, w0, fmaf(v1.y, w1, fmaf(v2.y, w2, fmaf(v3.y, w3, acc.y))));
        acc.z = fmaf(v0.z, w0, fmaf(v1.z, w1, fmaf(v2.z, w2, fmaf(v3.z, w3, acc.z))));
        acc.w = fmaf(v0.w, w0, fmaf(v1.w, w1, fmaf(v2.w, w2, fmaf(v3.w, w3, acc.w))));
    }
    for (; k < end; k++) {
        int s = g_csr[k];
        float w = g_dinv[s];
        float4 v = ld_h4(g_hh + (size_t)s * FIN, lane);
        acc.x = fmaf(v.x, w, acc.x);
        acc.y = fmaf(v.y, w, acc.y);
        acc.z = fmaf(v.z, w, acc.z);
        acc.w = fmaf(v.w, w, acc.w);
    }

    float4 bb = ((const float4*)b1)[lane];
    float zx = fmaxf(fmaf(acc.x, di, bb.x), 0.f);
    float zy = fmaxf(fmaf(acc.y, di, bb.y), 0.f);
    float zz = fmaxf(fmaf(acc.z, di, bb.z), 0.f);
    float zw = fmaxf(fmaf(acc.w, di, bb.w), 0.f);
    __half2 lo = __floats2half2_rn(zx, zy);
    __half2 hi = __floats2half2_rn(zz, zw);
    uint2 st;
    st.x = *(unsigned*)&lo;
    st.y = *(unsigned*)&hi;
    *((uint2*)(g_a1h + (size_t)node * FIN) + lane) = st;
}

// ---------------------------------------------------------------------------
// GEMM2: h2 = dinv * (a1 @ W2), register-tiled; a1 fp16 in, fp16 out
// ---------------------------------------------------------------------------
__global__ void k_gemm2(const float* __restrict__ W2, int n) {
    const int KC = 32;
    __shared__ float W2s[FIN * FOUT];        // 20 KB
    __shared__ float As[128 * 36];           // 18 KB (pad 36)

    int t    = threadIdx.x;
    int r    = t >> 1;
    int half = t & 1;
    int row0 = blockIdx.x * 128;

    for (int i = t; i < FIN * FOUT / 4; i += 256)
        ((float4*)W2s)[i] = ((const float4*)W2)[i];

    float4 acc[5];
#pragma unroll
    for (int j = 0; j < 5; j++) acc[j] = make_float4(0.f, 0.f, 0.f, 0.f);

    for (int kc = 0; kc < FIN; kc += KC) {
        for (int i = t; i < 128 * (KC / 4); i += 256) {
            int rr = i >> 3;
            int k4 = i & 7;
            int gr = row0 + rr;
            float4 v = make_float4(0.f, 0.f, 0.f, 0.f);
            if (gr < n) {
                uint2 u = *(const uint2*)(g_a1h + (size_t)gr * FIN + kc + k4 * 4);
                float2 lo = __half22float2(*(__half2*)&u.x);
                float2 hi = __half22float2(*(__half2*)&u.y);
                v = make_float4(lo.x, lo.y, hi.x, hi.y);
            }
            *(float4*)&As[rr * 36 + k4 * 4] = v;
        }
        __syncthreads();

#pragma unroll 4
        for (int kk = 0; kk < KC; kk++) {
            float av = As[r * 36 + kk];
            const float4* wp = (const float4*)(W2s + (kc + kk) * FOUT + half * 20);
            float4 w0 = wp[0];
            float4 w1 = wp[1];
            float4 w2 = wp[2];
            float4 w3 = wp[3];
            float4 w4 = wp[4];
            acc[0].x = fmaf(av, w0.x, acc[0].x); acc[0].y = fmaf(av, w0.y, acc[0].y);
            acc[0].z = fmaf(av, w0.z, acc[0].z); acc[0].w = fmaf(av, w0.w, acc[0].w);
            acc[1].x = fmaf(av, w1.x, acc[1].x); acc[1].y = fmaf(av, w1.y, acc[1].y);
            acc[1].z = fmaf(av, w1.z, acc[1].z); acc[1].w = fmaf(av, w1.w, acc[1].w);
            acc[2].x = fmaf(av, w2.x, acc[2].x); acc[2].y = fmaf(av, w2.y, acc[2].y);
            acc[2].z = fmaf(av, w2.z, acc[2].z); acc[2].w = fmaf(av, w2.w, acc[2].w);
            acc[3].x = fmaf(av, w3.x, acc[3].x); acc[3].y = fmaf(av, w3.y, acc[3].y);
            acc[3].z = fmaf(av, w3.z, acc[3].z); acc[3].w = fmaf(av, w3.w, acc[3].w);
            acc[4].x = fmaf(av, w4.x, acc[4].x); acc[4].y = fmaf(av, w4.y, acc[4].y);
            acc[4].z = fmaf(av, w4.z, acc[4].z); acc[4].w = fmaf(av, w4.w, acc[4].w);
        }
        __syncthreads();
    }

    int gr = row0 + r;
    if (gr < n) {
        float di = g_dinv[gr];
#pragma unroll
        for (int j = 0; j < 5; j++) {
            float4 o = acc[j];
            __half2 lo = __floats2half2_rn(o.x * di, o.y * di);
            __half2 hi = __floats2half2_rn(o.z * di, o.w * di);
            uint2 st;
            st.x = *(unsigned*)&lo;
            st.y = *(unsigned*)&hi;
            *(uint2*)(g_h2h + (size_t)gr * FOUT + half * 20 + j * 4) = st;
        }
    }
}

// ---------------------------------------------------------------------------
// agg2 (pull): out[d] = di * (sum h2[s] + h2[d]) + b2    [h2 pre-scaled fp16]
// warp per node; lanes 0..19 each handle cols 2*lane, 2*lane+1 (half2 loads)
// ---------------------------------------------------------------------------
__global__ void k_agg2(float* __restrict__ out, const float* __restrict__ b2,
                       int n) {
    int node = blockIdx.x * 8 + (threadIdx.x >> 5);
    int lane = threadIdx.x & 31;
    if (node >= n || lane >= 20) return;

    float di = g_dinv[node];
    unsigned u0 = *((const unsigned*)(g_h2h + (size_t)node * FOUT) + lane);
    float2 sv = __half22float2(*(__half2*)&u0);
    float a0 = sv.x, a1 = sv.y;

    int beg = g_rowptr[node], end = g_rowptr[node + 1];
    int k = beg;
    for (; k + 3 < end; k += 4) {
        unsigned v0 = *((const unsigned*)(g_h2h + (size_t)g_csr[k]     * FOUT) + lane);
        unsigned v1 = *((const unsigned*)(g_h2h + (size_t)g_csr[k + 1] * FOUT) + lane);
        unsigned v2 = *((const unsigned*)(g_h2h + (size_t)g_csr[k + 2] * FOUT) + lane);
        unsigned v3 = *((const unsigned*)(g_h2h + (size_t)g_csr[k + 3] * FOUT) + lane);
        float2 f0 = __half22float2(*(__half2*)&v0);
        float2 f1 = __half22float2(*(__half2*)&v1);
        float2 f2 = __half22float2(*(__half2*)&v2);
        float2 f3 = __half22float2(*(__half2*)&v3);
        a0 += (f0.x + f1.x) + (f2.x + f3.x);
        a1 += (f0.y + f1.y) + (f2.y + f3.y);
    }
    for (; k < end; k++) {
        unsigned v = *((const unsigned*)(g_h2h + (size_t)g_csr[k] * FOUT) + lane);
        float2 f = __half22float2(*(__half2*)&v);
        a0 += f.x;
        a1 += f.y;
    }

    float* op = out + (size_t)node * FOUT + 2 * lane;
    op[0] = fmaf(a0, di, b2[2 * lane]);
    op[1] = fmaf(a1, di, b2[2 * lane + 1]);
}

// ---------------------------------------------------------------------------
extern "C" void kernel_launch(void* const* d_in, const int* in_sizes, int n_in,
                              void* d_out, int out_size) {
    const float* x   = (const float*)d_in[0];
    const void*  ei  = d_in[1];
    const float* W1  = (const float*)d_in[2];
    const float* b1  = (const float*)d_in[3];
    const float* W2  = (const float*)d_in[4];
    const float* b2  = (const float*)d_in[5];
    float*       out = (float*)d_out;

    int n = in_sizes[0] / FIN;
    if (n > NMAX) n = NMAX;
    int E = in_sizes[1] / 2;
    if (E > EMAX) E = EMAX;

    int detect_cnt = 2048;
    if (detect_cnt > E) detect_cnt = E;
    int nsb = (n + SCAN_BLK - 1) / SCAN_BLK;

    k_zero_cnt    <<<(n + 255) / 256, 256>>>(n);                 // 1 (also inits g_is64)
    k_detect      <<<(detect_cnt + 255) / 256, 256>>>((const long long*)ei, n, detect_cnt); // 2
    k_convert_hist<<<(E + 255) / 256, 256>>>(ei, E);             // 3
    k_gemm1       <<<(n + 127) / 128, 256>>>(x, W1, n);          // 4 <- profiled
    k_scanA       <<<nsb, SCAN_BLK>>>(n);                        // 5
    k_scanB       <<<1, 256>>>(nsb, n, E);                       // 6
    k_scanC       <<<(n + 255) / 256, 256>>>(n);                 // 7
    k_fill        <<<(E + 255) / 256, 256>>>(E);                 // 8
    k_agg1        <<<(n + 7) / 8, 256>>>(b1, n);                 // 9
    k_gemm2       <<<(n + 127) / 128, 256>>>(W2, n);             // 10
    k_agg2        <<<(n + 7) / 8, 256>>>(out, b2, n);            // 11
}

// round 15
// speedup vs baseline: 1.3353x; 1.2171x over previous
#include <cuda_runtime.h>
#include <cuda_fp16.h>
#include <cstdint>

#define NMAX 100000
#define EMAX 1600000
#define FIN  128
#define FOUT 40
#define SCAN_BLK 1024

typedef unsigned long long ull;

// Scratch (static __device__ — no allocations allowed)
__device__ int    g_is64;
__device__ int    g_src32 [EMAX];
__device__ int    g_dst32 [EMAX];
__device__ int    g_csr   [EMAX];        // src ids grouped by dst
__device__ int    g_degi  [NMAX];
__device__ int    g_fill  [NMAX];
__device__ int    g_rowptr[NMAX + 1];
__device__ int    g_bsum  [(NMAX + SCAN_BLK - 1) / SCAN_BLK];
__device__ int    g_boff  [(NMAX + SCAN_BLK - 1) / SCAN_BLK];
__device__ float  g_dinv[NMAX];
__device__ __half g_hh  [(size_t)NMAX * FIN];   // x @ W1 (unscaled, fp16)
__device__ __half g_a1h [(size_t)NMAX * FIN];   // relu(layer-1 out), fp16
__device__ __half g_h2h [(size_t)NMAX * FOUT];  // dinv * (a1 @ W2), fp16

// ---------------------------------------------------------------------------
// preproc
// ---------------------------------------------------------------------------
__global__ void k_zero_cnt(int n) {
    int i = blockIdx.x * blockDim.x + threadIdx.x;
    if (i < n) { g_degi[i] = 0; g_fill[i] = 0; }
    if (i == 0) g_is64 = 1;
}

__global__ void k_detect(const long long* __restrict__ ei, int n, int count) {
    int i = blockIdx.x * blockDim.x + threadIdx.x;
    if (i < count) {
        long long v = ei[i];
        if (v < 0 || v >= (long long)n) atomicAnd(&g_is64, 0);
    }
}

__global__ void k_convert_hist(const void* __restrict__ ei, int E) {
    int e = blockIdx.x * blockDim.x + threadIdx.x;
    if (e >= E) return;
    int s, d;
    if (g_is64) {
        const long long* p = (const long long*)ei;
        s = (int)p[e];
        d = (int)p[E + e];
    } else {
        const int* p = (const int*)ei;
        s = p[e];
        d = p[E + e];
    }
    g_src32[e] = s;
    g_dst32[e] = d;
    atomicAdd(&g_degi[d], 1);
}

__global__ void k_scanA(int n) {
    __shared__ int sh[SCAN_BLK];
    int tid = threadIdx.x;
    int i = blockIdx.x * SCAN_BLK + tid;
    int v = (i < n) ? g_degi[i] : 0;
    if (i < n) g_dinv[i] = rsqrtf((float)v + 1.0f);  // +1 = self loop
    sh[tid] = v;
    __syncthreads();
    for (int off = 1; off < SCAN_BLK; off <<= 1) {
        int t = (tid >= off) ? sh[tid - off] : 0;
        __syncthreads();
        sh[tid] += t;
        __syncthreads();
    }
    if (i < n) g_rowptr[i] = sh[tid] - v;  // exclusive within block
    if (tid == SCAN_BLK - 1) g_bsum[blockIdx.x] = sh[tid];
}

__global__ void k_scanB(int nblocks, int n, int E) {
    __shared__ int sh[256];
    int tid = threadIdx.x;
    int carry = 0;
    for (int base = 0; base < nblocks; base += 256) {
        int i = base + tid;
        int v = (i < nblocks) ? g_bsum[i] : 0;
        sh[tid] = v;
        __syncthreads();
        for (int off = 1; off < 256; off <<= 1) {
            int t = (tid >= off) ? sh[tid - off] : 0;
            __syncthreads();
            sh[tid] += t;
            __syncthreads();
        }
        if (i < nblocks) g_boff[i] = carry + sh[tid] - v;
        __syncthreads();
        carry += sh[255];
        __syncthreads();
    }
    if (tid == 0) g_rowptr[n] = E;
}

__global__ void k_scanC(int n) {
    int i = blockIdx.x * blockDim.x + threadIdx.x;
    if (i < n) g_rowptr[i] += g_boff[i / SCAN_BLK];
}

__global__ void k_fill(int E) {
    int e = blockIdx.x * blockDim.x + threadIdx.x;
    if (e >= E) return;
    int d = g_dst32[e];
    int pos = g_rowptr[d] + atomicAdd(&g_fill[d], 1);
    g_csr[pos] = g_src32[e];
}

// ---------------------------------------------------------------------------
// GEMM1 (HMMA): h = x @ W1, fp16 inputs, fp32 accumulate, fp16 output.
// block = 256 threads (8 warps), tile = 128 rows x 128 cols, K chunked by 64.
// warp w -> rows 16w..16w+15, all 128 cols (16 n-tiles of 8).
// mma.sync.m16n8k16: A via ldmatrix.x4, B via ldmatrix.x4.trans (2 n-tiles).
// Smem swizzled: 16B chunk XOR (row&7)<<4 -> conflict-free ldmatrix.
// ---------------------------------------------------------------------------
__global__ void __launch_bounds__(256, 2)
k_gemm1(const float* __restrict__ x, const float* __restrict__ W, int n) {
    const int KC = 64;
    __shared__ __half Xs [128 * KC];   // 16 KB, [m][k] swizzled
    __shared__ __half Wsm[KC * FIN];   // 16 KB, [k][n] swizzled

    int t    = threadIdx.x;
    int lane = t & 31;
    int w    = t >> 5;
    int row0 = blockIdx.x * 128;

    unsigned xs_base = (unsigned)__cvta_generic_to_shared(Xs);
    unsigned ws_base = (unsigned)__cvta_generic_to_shared(Wsm);

    float acc[16][4];
#pragma unroll
    for (int nt = 0; nt < 16; nt++)
#pragma unroll
        for (int j = 0; j < 4; j++) acc[nt][j] = 0.f;

    for (int kc = 0; kc < FIN; kc += KC) {
        // stage X: 128 rows x KC cols, fp32 -> fp16, swizzled (8B stores)
        for (int i = t; i < 128 * KC / 4; i += 256) {
            int r  = i >> 4;               // KC/4 = 16 float4 per row
            int c4 = i & 15;
            int gr = row0 + r;
            float4 v = make_float4(0.f, 0.f, 0.f, 0.f);
            if (gr < n) v = ((const float4*)(x + (size_t)gr * FIN + kc))[c4];
            __half2 h01 = __floats2half2_rn(v.x, v.y);
            __half2 h23 = __floats2half2_rn(v.z, v.w);
            unsigned off = (r * (KC * 2) + c4 * 8) ^ ((r & 7) << 4);
            uint2 st;
            st.x = *(unsigned*)&h01;
            st.y = *(unsigned*)&h23;
            *(uint2*)((char*)Xs + off) = st;
        }
        // stage W: KC rows x 128 cols, fp32 -> fp16, swizzled
        for (int i = t; i < KC * FIN / 4; i += 256) {
            int r  = i >> 5;               // FIN/4 = 32 float4 per row
            int c4 = i & 31;
            float4 v = ((const float4*)(W + (size_t)(kc + r) * FIN))[c4];
            __half2 h01 = __floats2half2_rn(v.x, v.y);
            __half2 h23 = __floats2half2_rn(v.z, v.w);
            unsigned off = (r * (FIN * 2) + c4 * 8) ^ ((r & 7) << 4);
            uint2 st;
            st.x = *(unsigned*)&h01;
            st.y = *(unsigned*)&h23;
            *(uint2*)((char*)Wsm + off) = st;
        }
        __syncthreads();

#pragma unroll
        for (int kk = 0; kk < KC / 16; kk++) {
            // A fragment: 16x16 tile at rows 16w..+15, k cols kk*16..+15
            unsigned a0, a1, a2, a3;
            {
                int ar = 16 * w + (lane & 15);
                unsigned off = (ar * (KC * 2) + kk * 32 + ((lane >> 4) << 4))
                               ^ ((ar & 7) << 4);
                asm volatile(
                    "ldmatrix.sync.aligned.m8n8.x4.shared.b16 {%0,%1,%2,%3}, [%4];"
                    : "=r"(a0), "=r"(a1), "=r"(a2), "=r"(a3)
                    : "r"(xs_base + off));
            }
#pragma unroll
            for (int np = 0; np < 8; np++) {   // pairs of n-tiles
                unsigned b0, b1, b2, b3;
                {
                    int br = kk * 16 + (lane & 15);
                    int ntc = np * 2 + (lane >> 4);   // n-tile column for this half
                    unsigned off = (br * (FIN * 2) + ntc * 16) ^ ((br & 7) << 4);
                    asm volatile(
                        "ldmatrix.sync.aligned.m8n8.x4.trans.shared.b16 {%0,%1,%2,%3}, [%4];"
                        : "=r"(b0), "=r"(b1), "=r"(b2), "=r"(b3)
                        : "r"(ws_base + off));
                }
                float* d0 = acc[np * 2];
                float* d1 = acc[np * 2 + 1];
                asm volatile(
                    "mma.sync.aligned.m16n8k16.row.col.f32.f16.f16.f32 "
                    "{%0,%1,%2,%3}, {%4,%5,%6,%7}, {%8,%9}, {%0,%1,%2,%3};"
                    : "+f"(d0[0]), "+f"(d0[1]), "+f"(d0[2]), "+f"(d0[3])
                    : "r"(a0), "r"(a1), "r"(a2), "r"(a3), "r"(b0), "r"(b1));
                asm volatile(
                    "mma.sync.aligned.m16n8k16.row.col.f32.f16.f16.f32 "
                    "{%0,%1,%2,%3}, {%4,%5,%6,%7}, {%8,%9}, {%0,%1,%2,%3};"
                    : "+f"(d1[0]), "+f"(d1[1]), "+f"(d1[2]), "+f"(d1[3])
                    : "r"(a0), "r"(a1), "r"(a2), "r"(a3), "r"(b2), "r"(b3));
            }
        }
        __syncthreads();
    }

    // epilogue: acc (16 rows x 128 cols per warp) -> fp16 g_hh
    {
        int rlo = row0 + 16 * w + (lane >> 2);
        int rhi = rlo + 8;
        int cbase = (lane & 3) * 2;
#pragma unroll
        for (int nt = 0; nt < 16; nt++) {
            int col = nt * 8 + cbase;
            if (rlo < n) {
                __half2 p = __floats2half2_rn(acc[nt][0], acc[nt][1]);
                *(unsigned*)(g_hh + (size_t)rlo * FIN + col) = *(unsigned*)&p;
            }
            if (rhi < n) {
                __half2 p = __floats2half2_rn(acc[nt][2], acc[nt][3]);
                *(unsigned*)(g_hh + (size_t)rhi * FIN + col) = *(unsigned*)&p;
            }
        }
    }
}

// ---------------------------------------------------------------------------
// agg1 (pull): a1[d] = relu( di * (sum_s dinv[s]*h[s] + di*h[d]) + b1 )
// warp per node, lane holds 4 cols; fp16 gathers, fp16 store
// ---------------------------------------------------------------------------
__device__ __forceinline__ float4 ld_h4(const __half* p, int lane) {
    uint2 u = *((const uint2*)p + lane);
    float2 lo = __half22float2(*(__half2*)&u.x);
    float2 hi = __half22float2(*(__half2*)&u.y);
    return make_float4(lo.x, lo.y, hi.x, hi.y);
}

__global__ void k_agg1(const float* __restrict__ b1, int n) {
    int node = blockIdx.x * 8 + (threadIdx.x >> 5);
    int lane = threadIdx.x & 31;
    if (node >= n) return;

    float di = g_dinv[node];
    float4 sv = ld_h4(g_hh + (size_t)node * FIN, lane);
    float4 acc = make_float4(sv.x * di, sv.y * di, sv.z * di, sv.w * di);

    int beg = g_rowptr[node], end = g_rowptr[node + 1];
    int k = beg;
    for (; k + 3 < end; k += 4) {
        int s0 = g_csr[k],     s1 = g_csr[k + 1];
        int s2 = g_csr[k + 2], s3 = g_csr[k + 3];
        float w0 = g_dinv[s0], w1 = g_dinv[s1];
        float w2 = g_dinv[s2], w3 = g_dinv[s3];
        float4 v0 = ld_h4(g_hh + (size_t)s0 * FIN, lane);
        float4 v1 = ld_h4(g_hh + (size_t)s1 * FIN, lane);
        float4 v2 = ld_h4(g_hh + (size_t)s2 * FIN, lane);
        float4 v3 = ld_h4(g_hh + (size_t)s3 * FIN, lane);
        acc.x = fmaf(v0.x, w0, fmaf(v1.x, w1, fmaf(v2.x, w2, fmaf(v3.x, w3, acc.x))));
        acc.y = fmaf(v0.y, w0, fmaf(v1.y, w1, fmaf(v2.y, w2, fmaf(v3.y, w3, acc.y))));
        acc.z = fmaf(v0.z, w0, fmaf(v1.z, w1, fmaf(v2.z, w2, fmaf(v3.z, w3, acc.z))));
        acc.w = fmaf(v0.w, w0, fmaf(v1.w, w1, fmaf(v2.w, w2, fmaf(v3.w, w3, acc.w))));
    }
    for (; k < end; k++) {
        int s = g_csr[k];
        float w = g_dinv[s];
        float4 v = ld_h4(g_hh + (size_t)s * FIN, lane);
        acc.x = fmaf(v.x, w, acc.x);
        acc.y = fmaf(v.y, w, acc.y);
        acc.z = fmaf(v.z, w, acc.z);
        acc.w = fmaf(v.w, w, acc.w);
    }

    float4 bb = ((const float4*)b1)[lane];
    float zx = fmaxf(fmaf(acc.x, di, bb.x), 0.f);
    float zy = fmaxf(fmaf(acc.y, di, bb.y), 0.f);
    float zz = fmaxf(fmaf(acc.z, di, bb.z), 0.f);
    float zw = fmaxf(fmaf(acc.w, di, bb.w), 0.f);
    __half2 lo = __floats2half2_rn(zx, zy);
    __half2 hi = __floats2half2_rn(zz, zw);
    uint2 st;
    st.x = *(unsigned*)&lo;
    st.y = *(unsigned*)&hi;
    *((uint2*)(g_a1h + (size_t)node * FIN) + lane) = st;
}

// ---------------------------------------------------------------------------
// GEMM2: h2 = dinv * (a1 @ W2), register-tiled; a1 fp16 in, fp16 out
// ---------------------------------------------------------------------------
__global__ void k_gemm2(const float* __restrict__ W2, int n) {
    const int KC = 32;
    __shared__ float W2s[FIN * FOUT];        // 20 KB
    __shared__ float As[128 * 36];           // 18 KB (pad 36)

    int t    = threadIdx.x;
    int r    = t >> 1;
    int half = t & 1;
    int row0 = blockIdx.x * 128;

    for (int i = t; i < FIN * FOUT / 4; i += 256)
        ((float4*)W2s)[i] = ((const float4*)W2)[i];

    float4 acc[5];
#pragma unroll
    for (int j = 0; j < 5; j++) acc[j] = make_float4(0.f, 0.f, 0.f, 0.f);

    for (int kc = 0; kc < FIN; kc += KC) {
        for (int i = t; i < 128 * (KC / 4); i += 256) {
            int rr = i >> 3;
            int k4 = i & 7;
            int gr = row0 + rr;
            float4 v = make_float4(0.f, 0.f, 0.f, 0.f);
            if (gr < n) {
                uint2 u = *(const uint2*)(g_a1h + (size_t)gr * FIN + kc + k4 * 4);
                float2 lo = __half22float2(*(__half2*)&u.x);
                float2 hi = __half22float2(*(__half2*)&u.y);
                v = make_float4(lo.x, lo.y, hi.x, hi.y);
            }
            *(float4*)&As[rr * 36 + k4 * 4] = v;
        }
        __syncthreads();

#pragma unroll 4
        for (int kk = 0; kk < KC; kk++) {
            float av = As[r * 36 + kk];
            const float4* wp = (const float4*)(W2s + (kc + kk) * FOUT + half * 20);
            float4 w0 = wp[0];
            float4 w1 = wp[1];
            float4 w2 = wp[2];
            float4 w3 = wp[3];
            float4 w4 = wp[4];
            acc[0].x = fmaf(av, w0.x, acc[0].x); acc[0].y = fmaf(av, w0.y, acc[0].y);
            acc[0].z = fmaf(av, w0.z, acc[0].z); acc[0].w = fmaf(av, w0.w, acc[0].w);
            acc[1].x = fmaf(av, w1.x, acc[1].x); acc[1].y = fmaf(av, w1.y, acc[1].y);
            acc[1].z = fmaf(av, w1.z, acc[1].z); acc[1].w = fmaf(av, w1.w, acc[1].w);
            acc[2].x = fmaf(av, w2.x, acc[2].x); acc[2].y = fmaf(av, w2.y, acc[2].y);
            acc[2].z = fmaf(av, w2.z, acc[2].z); acc[2].w = fmaf(av, w2.w, acc[2].w);
            acc[3].x = fmaf(av, w3.x, acc[3].x); acc[3].y = fmaf(av, w3.y, acc[3].y);
            acc[3].z = fmaf(av, w3.z, acc[3].z); acc[3].w = fmaf(av, w3.w, acc[3].w);
            acc[4].x = fmaf(av, w4.x, acc[4].x); acc[4].y = fmaf(av, w4.y, acc[4].y);
            acc[4].z = fmaf(av, w4.z, acc[4].z); acc[4].w = fmaf(av, w4.w, acc[4].w);
        }
        __syncthreads();
    }

    int gr = row0 + r;
    if (gr < n) {
        float di = g_dinv[gr];
#pragma unroll
        for (int j = 0; j < 5; j++) {
            float4 o = acc[j];
            __half2 lo = __floats2half2_rn(o.x * di, o.y * di);
            __half2 hi = __floats2half2_rn(o.z * di, o.w * di);
            uint2 st;
            st.x = *(unsigned*)&lo;
            st.y = *(unsigned*)&hi;
            *(uint2*)(g_h2h + (size_t)gr * FOUT + half * 20 + j * 4) = st;
        }
    }
}

// ---------------------------------------------------------------------------
// agg2 (pull): out[d] = di * (sum h2[s] + h2[d]) + b2    [h2 pre-scaled fp16]
// warp per node; lanes 0..19 each handle cols 2*lane, 2*lane+1 (half2 loads)
// ---------------------------------------------------------------------------
__global__ void k_agg2(float* __restrict__ out, const float* __restrict__ b2,
                       int n) {
    int node = blockIdx.x * 8 + (threadIdx.x >> 5);
    int lane = threadIdx.x & 31;
    if (node >= n || lane >= 20) return;

    float di = g_dinv[node];
    unsigned u0 = *((const unsigned*)(g_h2h + (size_t)node * FOUT) + lane);
    float2 sv = __half22float2(*(__half2*)&u0);
    float a0 = sv.x, a1 = sv.y;

    int beg = g_rowptr[node], end = g_rowptr[node + 1];
    int k = beg;
    for (; k + 3 < end; k += 4) {
        unsigned v0 = *((const unsigned*)(g_h2h + (size_t)g_csr[k]     * FOUT) + lane);
        unsigned v1 = *((const unsigned*)(g_h2h + (size_t)g_csr[k + 1] * FOUT) + lane);
        unsigned v2 = *((const unsigned*)(g_h2h + (size_t)g_csr[k + 2] * FOUT) + lane);
        unsigned v3 = *((const unsigned*)(g_h2h + (size_t)g_csr[k + 3] * FOUT) + lane);
        float2 f0 = __half22float2(*(__half2*)&v0);
        float2 f1 = __half22float2(*(__half2*)&v1);
        float2 f2 = __half22float2(*(__half2*)&v2);
        float2 f3 = __half22float2(*(__half2*)&v3);
        a0 += (f0.x + f1.x) + (f2.x + f3.x);
        a1 += (f0.y + f1.y) + (f2.y + f3.y);
    }
    for (; k < end; k++) {
        unsigned v = *((const unsigned*)(g_h2h + (size_t)g_csr[k] * FOUT) + lane);
        float2 f = __half22float2(*(__half2*)&v);
        a0 += f.x;
        a1 += f.y;
    }

    float* op = out + (size_t)node * FOUT + 2 * lane;
    op[0] = fmaf(a0, di, b2[2 * lane]);
    op[1] = fmaf(a1, di, b2[2 * lane + 1]);
}

// ---------------------------------------------------------------------------
extern "C" void kernel_launch(void* const* d_in, const int* in_sizes, int n_in,
                              void* d_out, int out_size) {
    const float* x   = (const float*)d_in[0];
    const void*  ei  = d_in[1];
    const float* W1  = (const float*)d_in[2];
    const float* b1  = (const float*)d_in[3];
    const float* W2  = (const float*)d_in[4];
    const float* b2  = (const float*)d_in[5];
    float*       out = (float*)d_out;

    int n = in_sizes[0] / FIN;
    if (n > NMAX) n = NMAX;
    int E = in_sizes[1] / 2;
    if (E > EMAX) E = EMAX;

    int detect_cnt = 2048;
    if (detect_cnt > E) detect_cnt = E;
    int nsb = (n + SCAN_BLK - 1) / SCAN_BLK;

    k_zero_cnt    <<<(n + 255) / 256, 256>>>(n);                 // 1 (also inits g_is64)
    k_detect      <<<(detect_cnt + 255) / 256, 256>>>((const long long*)ei, n, detect_cnt); // 2
    k_convert_hist<<<(E + 255) / 256, 256>>>(ei, E);             // 3
    k_gemm1       <<<(n + 127) / 128, 256>>>(x, W1, n);          // 4 <- profiled
    k_scanA       <<<nsb, SCAN_BLK>>>(n);                        // 5
    k_scanB       <<<1, 256>>>(nsb, n, E);                       // 6
    k_scanC       <<<(n + 255) / 256, 256>>>(n);                 // 7
    k_fill        <<<(E + 255) / 256, 256>>>(E);                 // 8
    k_agg1        <<<(n + 7) / 8, 256>>>(b1, n);                 // 9
    k_gemm2       <<<(n + 127) / 128, 256>>>(W2, n);             // 10
    k_agg2        <<<(n + 7) / 8, 256>>>(out, b2, n);            // 11
}

// round 16
// speedup vs baseline: 1.5971x; 1.1961x over previous
#include <cuda_runtime.h>
#include <cuda_fp16.h>
#include <cstdint>

#define NMAX 100000
#define EMAX 1600000
#define FIN  128
#define FOUT 40
#define SCAN_BLK 1024

typedef unsigned long long ull;

// Scratch (static __device__ — no allocations allowed)
__device__ int    g_is64;
__device__ int    g_src32 [EMAX];
__device__ int    g_dst32 [EMAX];
__device__ int    g_csr   [EMAX];        // src ids grouped by dst
__device__ int    g_degi  [NMAX];
__device__ int    g_fill  [NMAX];
__device__ int    g_rowptr[NMAX + 1];
__device__ int    g_bsum  [(NMAX + SCAN_BLK - 1) / SCAN_BLK];
__device__ int    g_boff  [(NMAX + SCAN_BLK - 1) / SCAN_BLK];
__device__ float  g_dinv[NMAX];
__device__ __half g_hh  [(size_t)NMAX * FIN];   // x @ W1 (unscaled, fp16)
__device__ __half g_a1h [(size_t)NMAX * FIN];   // relu(layer-1 out), fp16
__device__ __half g_h2h [(size_t)NMAX * FOUT];  // dinv * (a1 @ W2), fp16

// ---------------------------------------------------------------------------
// preproc
// ---------------------------------------------------------------------------
__global__ void k_zero_cnt(int n) {
    int i = blockIdx.x * blockDim.x + threadIdx.x;
    if (i < n) { g_degi[i] = 0; g_fill[i] = 0; }
    if (i == 0) g_is64 = 1;
}

__global__ void k_detect(const long long* __restrict__ ei, int n, int count) {
    int i = blockIdx.x * blockDim.x + threadIdx.x;
    if (i < count) {
        long long v = ei[i];
        if (v < 0 || v >= (long long)n) atomicAnd(&g_is64, 0);
    }
}

__global__ void k_convert_hist(const void* __restrict__ ei, int E) {
    int e = blockIdx.x * blockDim.x + threadIdx.x;
    if (e >= E) return;
    int s, d;
    if (g_is64) {
        const long long* p = (const long long*)ei;
        s = (int)p[e];
        d = (int)p[E + e];
    } else {
        const int* p = (const int*)ei;
        s = p[e];
        d = p[E + e];
    }
    g_src32[e] = s;
    g_dst32[e] = d;
    atomicAdd(&g_degi[d], 1);
}

__global__ void k_scanA(int n) {
    __shared__ int sh[SCAN_BLK];
    int tid = threadIdx.x;
    int i = blockIdx.x * SCAN_BLK + tid;
    int v = (i < n) ? g_degi[i] : 0;
    if (i < n) g_dinv[i] = rsqrtf((float)v + 1.0f);  // +1 = self loop
    sh[tid] = v;
    __syncthreads();
    for (int off = 1; off < SCAN_BLK; off <<= 1) {
        int t = (tid >= off) ? sh[tid - off] : 0;
        __syncthreads();
        sh[tid] += t;
        __syncthreads();
    }
    if (i < n) g_rowptr[i] = sh[tid] - v;  // exclusive within block
    if (tid == SCAN_BLK - 1) g_bsum[blockIdx.x] = sh[tid];
}

__global__ void k_scanB(int nblocks, int n, int E) {
    __shared__ int sh[256];
    int tid = threadIdx.x;
    int carry = 0;
    for (int base = 0; base < nblocks; base += 256) {
        int i = base + tid;
        int v = (i < nblocks) ? g_bsum[i] : 0;
        sh[tid] = v;
        __syncthreads();
        for (int off = 1; off < 256; off <<= 1) {
            int t = (tid >= off) ? sh[tid - off] : 0;
            __syncthreads();
            sh[tid] += t;
            __syncthreads();
        }
        if (i < nblocks) g_boff[i] = carry + sh[tid] - v;
        __syncthreads();
        carry += sh[255];
        __syncthreads();
    }
    if (tid == 0) g_rowptr[n] = E;
}

__global__ void k_scanC(int n) {
    int i = blockIdx.x * blockDim.x + threadIdx.x;
    if (i < n) g_rowptr[i] += g_boff[i / SCAN_BLK];
}

__global__ void k_fill(int E) {
    int e = blockIdx.x * blockDim.x + threadIdx.x;
    if (e >= E) return;
    int d = g_dst32[e];
    int pos = g_rowptr[d] + atomicAdd(&g_fill[d], 1);
    g_csr[pos] = g_src32[e];
}

// ---------------------------------------------------------------------------
// GEMM1 (HMMA): h = x @ W1, fp16 inputs, fp32 accumulate, fp16 output.
// EXACT R15 configuration (measured 45.5 us) — do not modify.
// ---------------------------------------------------------------------------
__global__ void __launch_bounds__(256, 2)
k_gemm1(const float* __restrict__ x, const float* __restrict__ W, int n) {
    const int KC = 64;
    __shared__ __half Xs [128 * KC];   // 16 KB, [m][k] swizzled
    __shared__ __half Wsm[KC * FIN];   // 16 KB, [k][n] swizzled

    int t    = threadIdx.x;
    int lane = t & 31;
    int w    = t >> 5;
    int row0 = blockIdx.x * 128;

    unsigned xs_base = (unsigned)__cvta_generic_to_shared(Xs);
    unsigned ws_base = (unsigned)__cvta_generic_to_shared(Wsm);

    float acc[16][4];
#pragma unroll
    for (int nt = 0; nt < 16; nt++)
#pragma unroll
        for (int j = 0; j < 4; j++) acc[nt][j] = 0.f;

    for (int kc = 0; kc < FIN; kc += KC) {
        for (int i = t; i < 128 * KC / 4; i += 256) {
            int r  = i >> 4;
            int c4 = i & 15;
            int gr = row0 + r;
            float4 v = make_float4(0.f, 0.f, 0.f, 0.f);
            if (gr < n) v = ((const float4*)(x + (size_t)gr * FIN + kc))[c4];
            __half2 h01 = __floats2half2_rn(v.x, v.y);
            __half2 h23 = __floats2half2_rn(v.z, v.w);
            unsigned off = (r * (KC * 2) + c4 * 8) ^ ((r & 7) << 4);
            uint2 st;
            st.x = *(unsigned*)&h01;
            st.y = *(unsigned*)&h23;
            *(uint2*)((char*)Xs + off) = st;
        }
        for (int i = t; i < KC * FIN / 4; i += 256) {
            int r  = i >> 5;
            int c4 = i & 31;
            float4 v = ((const float4*)(W + (size_t)(kc + r) * FIN))[c4];
            __half2 h01 = __floats2half2_rn(v.x, v.y);
            __half2 h23 = __floats2half2_rn(v.z, v.w);
            unsigned off = (r * (FIN * 2) + c4 * 8) ^ ((r & 7) << 4);
            uint2 st;
            st.x = *(unsigned*)&h01;
            st.y = *(unsigned*)&h23;
            *(uint2*)((char*)Wsm + off) = st;
        }
        __syncthreads();

#pragma unroll
        for (int kk = 0; kk < KC / 16; kk++) {
            unsigned a0, a1, a2, a3;
            {
                int ar = 16 * w + (lane & 15);
                unsigned off = (ar * (KC * 2) + kk * 32 + ((lane >> 4) << 4))
                               ^ ((ar & 7) << 4);
                asm volatile(
                    "ldmatrix.sync.aligned.m8n8.x4.shared.b16 {%0,%1,%2,%3}, [%4];"
                    : "=r"(a0), "=r"(a1), "=r"(a2), "=r"(a3)
                    : "r"(xs_base + off));
            }
#pragma unroll
            for (int np = 0; np < 8; np++) {
                unsigned b0, b1, b2, b3;
                {
                    int br = kk * 16 + (lane & 15);
                    int ntc = np * 2 + (lane >> 4);
                    unsigned off = (br * (FIN * 2) + ntc * 16) ^ ((br & 7) << 4);
                    asm volatile(
                        "ldmatrix.sync.aligned.m8n8.x4.trans.shared.b16 {%0,%1,%2,%3}, [%4];"
                        : "=r"(b0), "=r"(b1), "=r"(b2), "=r"(b3)
                        : "r"(ws_base + off));
                }
                float* d0 = acc[np * 2];
                float* d1 = acc[np * 2 + 1];
                asm volatile(
                    "mma.sync.aligned.m16n8k16.row.col.f32.f16.f16.f32 "
                    "{%0,%1,%2,%3}, {%4,%5,%6,%7}, {%8,%9}, {%0,%1,%2,%3};"
                    : "+f"(d0[0]), "+f"(d0[1]), "+f"(d0[2]), "+f"(d0[3])
                    : "r"(a0), "r"(a1), "r"(a2), "r"(a3), "r"(b0), "r"(b1));
                asm volatile(
                    "mma.sync.aligned.m16n8k16.row.col.f32.f16.f16.f32 "
                    "{%0,%1,%2,%3}, {%4,%5,%6,%7}, {%8,%9}, {%0,%1,%2,%3};"
                    : "+f"(d1[0]), "+f"(d1[1]), "+f"(d1[2]), "+f"(d1[3])
                    : "r"(a0), "r"(a1), "r"(a2), "r"(a3), "r"(b2), "r"(b3));
            }
        }
        __syncthreads();
    }

    {
        int rlo = row0 + 16 * w + (lane >> 2);
        int rhi = rlo + 8;
        int cbase = (lane & 3) * 2;
#pragma unroll
        for (int nt = 0; nt < 16; nt++) {
            int col = nt * 8 + cbase;
            if (rlo < n) {
                __half2 p = __floats2half2_rn(acc[nt][0], acc[nt][1]);
                *(unsigned*)(g_hh + (size_t)rlo * FIN + col) = *(unsigned*)&p;
            }
            if (rhi < n) {
                __half2 p = __floats2half2_rn(acc[nt][2], acc[nt][3]);
                *(unsigned*)(g_hh + (size_t)rhi * FIN + col) = *(unsigned*)&p;
            }
        }
    }
}

// ---------------------------------------------------------------------------
// agg1 (pull): a1[d] = relu( di * (sum_s dinv[s]*h[s] + di*h[d]) + b1 )
// warp per node, lane holds 4 cols; fp16 gathers, fp16 store
// ---------------------------------------------------------------------------
__device__ __forceinline__ float4 ld_h4(const __half* p, int lane) {
    uint2 u = *((const uint2*)p + lane);
    float2 lo = __half22float2(*(__half2*)&u.x);
    float2 hi = __half22float2(*(__half2*)&u.y);
    return make_float4(lo.x, lo.y, hi.x, hi.y);
}

__global__ void k_agg1(const float* __restrict__ b1, int n) {
    int node = blockIdx.x * 8 + (threadIdx.x >> 5);
    int lane = threadIdx.x & 31;
    if (node >= n) return;

    float di = g_dinv[node];
    float4 sv = ld_h4(g_hh + (size_t)node * FIN, lane);
    float4 acc = make_float4(sv.x * di, sv.y * di, sv.z * di, sv.w * di);

    int beg = g_rowptr[node], end = g_rowptr[node + 1];
    int k = beg;
    for (; k + 3 < end; k += 4) {
        int s0 = g_csr[k],     s1 = g_csr[k + 1];
        int s2 = g_csr[k + 2], s3 = g_csr[k + 3];
        float w0 = g_dinv[s0], w1 = g_dinv[s1];
        float w2 = g_dinv[s2], w3 = g_dinv[s3];
        float4 v0 = ld_h4(g_hh + (size_t)s0 * FIN, lane);
        float4 v1 = ld_h4(g_hh + (size_t)s1 * FIN, lane);
        float4 v2 = ld_h4(g_hh + (size_t)s2 * FIN, lane);
        float4 v3 = ld_h4(g_hh + (size_t)s3 * FIN, lane);
        acc.x = fmaf(v0.x, w0, fmaf(v1.x, w1, fmaf(v2.x, w2, fmaf(v3.x, w3, acc.x))));
        acc.y = fmaf(v0.y, w0, fmaf(v1.y, w1, fmaf(v2.y, w2, fmaf(v3.y, w3, acc.y))));
        acc.z = fmaf(v0.z, w0, fmaf(v1.z, w1, fmaf(v2.z, w2, fmaf(v3.z, w3, acc.z))));
        acc.w = fmaf(v0.w, w0, fmaf(v1.w, w1, fmaf(v2.w, w2, fmaf(v3.w, w3, acc.w))));
    }
    for (; k < end; k++) {
        int s = g_csr[k];
        float w = g_dinv[s];
        float4 v = ld_h4(g_hh + (size_t)s * FIN, lane);
        acc.x = fmaf(v.x, w, acc.x);
        acc.y = fmaf(v.y, w, acc.y);
        acc.z = fmaf(v.z, w, acc.z);
        acc.w = fmaf(v.w, w, acc.w);
    }

    float4 bb = ((const float4*)b1)[lane];
    float zx = fmaxf(fmaf(acc.x, di, bb.x), 0.f);
    float zy = fmaxf(fmaf(acc.y, di, bb.y), 0.f);
    float zz = fmaxf(fmaf(acc.z, di, bb.z), 0.f);
    float zw = fmaxf(fmaf(acc.w, di, bb.w), 0.f);
    __half2 lo = __floats2half2_rn(zx, zy);
    __half2 hi = __floats2half2_rn(zz, zw);
    uint2 st;
    st.x = *(unsigned*)&lo;
    st.y = *(unsigned*)&hi;
    *((uint2*)(g_a1h + (size_t)node * FIN) + lane) = st;
}

// ---------------------------------------------------------------------------
// GEMM2 (HMMA): h2 = dinv * (a1 @ W2), fp16 in/out, fp32 accumulate.
// block = 256 threads (8 warps), tile = 128 rows x 48 cols (40 real + 8 pad),
// K = 128 in ONE stage. Same validated ldmatrix/mma pattern as gemm1.
// As: [m][k] swizzled, row stride 256B (32 KB).
// Ws2: [k][n] swizzled, 64 halves/row padded (16 KB), pad chunks zeroed.
// ---------------------------------------------------------------------------
__global__ void k_gemm2(const float* __restrict__ W2, int n) {
    __shared__ __half As [128 * 128];  // 32 KB
    __shared__ __half Ws2[128 * 64];   // 16 KB

    int t    = threadIdx.x;
    int lane = t & 31;
    int w    = t >> 5;
    int row0 = blockIdx.x * 128;

    unsigned as_base = (unsigned)__cvta_generic_to_shared(As);
    unsigned ws_base = (unsigned)__cvta_generic_to_shared(Ws2);

    // stage A (a1h): 128 rows x 128 halves, 16B chunks, swizzled
    for (int i = t; i < 128 * 16; i += 256) {
        int r = i >> 4;
        int c = i & 15;
        int gr = row0 + r;
        uint4 v = make_uint4(0u, 0u, 0u, 0u);
        if (gr < n) v = *(const uint4*)(g_a1h + (size_t)gr * FIN + c * 8);
        unsigned off = (r * 256 + ((c * 16) ^ ((r & 7) << 4)));
        *(uint4*)((char*)As + off) = v;
    }
    // stage W2: 128 k-rows x 64 cols (chunks 0..4 real = 40 cols, 5..7 zero)
    for (int i = t; i < 128 * 8; i += 256) {
        int r = i >> 3;
        int c = i & 7;
        uint4 st = make_uint4(0u, 0u, 0u, 0u);
        if (c < 5) {
            const float4* src = (const float4*)(W2 + (size_t)r * FOUT + c * 8);
            float4 v0 = src[0];
            float4 v1 = src[1];
            __half2 h0 = __floats2half2_rn(v0.x, v0.y);
            __half2 h1 = __floats2half2_rn(v0.z, v0.w);
            __half2 h2 = __floats2half2_rn(v1.x, v1.y);
            __half2 h3 = __floats2half2_rn(v1.z, v1.w);
            st.x = *(unsigned*)&h0; st.y = *(unsigned*)&h1;
            st.z = *(unsigned*)&h2; st.w = *(unsigned*)&h3;
        }
        unsigned off = (r * 128 + ((c * 16) ^ ((r & 7) << 4)));
        *(uint4*)((char*)Ws2 + off) = st;
    }
    __syncthreads();

    float acc[6][4];
#pragma unroll
    for (int nt = 0; nt < 6; nt++)
#pragma unroll
        for (int j = 0; j < 4; j++) acc[nt][j] = 0.f;

#pragma unroll
    for (int kk = 0; kk < 8; kk++) {
        unsigned a0, a1, a2, a3;
        {
            int ar = 16 * w + (lane & 15);
            unsigned off = (ar * 256 + ((kk * 32 + ((lane >> 4) << 4))
                           ^ ((ar & 7) << 4)));
            asm volatile(
                "ldmatrix.sync.aligned.m8n8.x4.shared.b16 {%0,%1,%2,%3}, [%4];"
                : "=r"(a0), "=r"(a1), "=r"(a2), "=r"(a3)
                : "r"(as_base + off));
        }
#pragma unroll
        for (int np = 0; np < 3; np++) {
            unsigned b0, b1, b2, b3;
            {
                int br = kk * 16 + (lane & 15);
                int ntc = np * 2 + (lane >> 4);
                unsigned off = (br * 128 + ((ntc * 16) ^ ((br & 7) << 4)));
                asm volatile(
                    "ldmatrix.sync.aligned.m8n8.x4.trans.shared.b16 {%0,%1,%2,%3}, [%4];"
                    : "=r"(b0), "=r"(b1), "=r"(b2), "=r"(b3)
                    : "r"(ws_base + off));
            }
            float* d0 = acc[np * 2];
            float* d1 = acc[np * 2 + 1];
            asm volatile(
                "mma.sync.aligned.m16n8k16.row.col.f32.f16.f16.f32 "
                "{%0,%1,%2,%3}, {%4,%5,%6,%7}, {%8,%9}, {%0,%1,%2,%3};"
                : "+f"(d0[0]), "+f"(d0[1]), "+f"(d0[2]), "+f"(d0[3])
                : "r"(a0), "r"(a1), "r"(a2), "r"(a3), "r"(b0), "r"(b1));
            asm volatile(
                "mma.sync.aligned.m16n8k16.row.col.f32.f16.f16.f32 "
                "{%0,%1,%2,%3}, {%4,%5,%6,%7}, {%8,%9}, {%0,%1,%2,%3};"
                : "+f"(d1[0]), "+f"(d1[1]), "+f"(d1[2]), "+f"(d1[3])
                : "r"(a0), "r"(a1), "r"(a2), "r"(a3), "r"(b2), "r"(b3));
        }
    }

    // epilogue: scale by dinv, store cols < 40 (n-tiles 0..4)
    {
        int rlo = row0 + 16 * w + (lane >> 2);
        int rhi = rlo + 8;
        int cbase = (lane & 3) * 2;
        float dlo = (rlo < n) ? g_dinv[rlo] : 0.f;
        float dhi = (rhi < n) ? g_dinv[rhi] : 0.f;
#pragma unroll
        for (int nt = 0; nt < 5; nt++) {
            int col = nt * 8 + cbase;
            if (rlo < n) {
                __half2 p = __floats2half2_rn(acc[nt][0] * dlo, acc[nt][1] * dlo);
                *(unsigned*)(g_h2h + (size_t)rlo * FOUT + col) = *(unsigned*)&p;
            }
            if (rhi < n) {
                __half2 p = __floats2half2_rn(acc[nt][2] * dhi, acc[nt][3] * dhi);
                *(unsigned*)(g_h2h + (size_t)rhi * FOUT + col) = *(unsigned*)&p;
            }
        }
    }
}

// ---------------------------------------------------------------------------
// agg2 (pull): out[d] = di * (sum h2[s] + h2[d]) + b2    [h2 pre-scaled fp16]
// warp per node; lanes 0..19 each handle cols 2*lane, 2*lane+1 (half2 loads)
// ---------------------------------------------------------------------------
__global__ void k_agg2(float* __restrict__ out, const float* __restrict__ b2,
                       int n) {
    int node = blockIdx.x * 8 + (threadIdx.x >> 5);
    int lane = threadIdx.x & 31;
    if (node >= n || lane >= 20) return;

    float di = g_dinv[node];
    unsigned u0 = *((const unsigned*)(g_h2h + (size_t)node * FOUT) + lane);
    float2 sv = __half22float2(*(__half2*)&u0);
    float a0 = sv.x, a1 = sv.y;

    int beg = g_rowptr[node], end = g_rowptr[node + 1];
    int k = beg;
    for (; k + 3 < end; k += 4) {
        unsigned v0 = *((const unsigned*)(g_h2h + (size_t)g_csr[k]     * FOUT) + lane);
        unsigned v1 = *((const unsigned*)(g_h2h + (size_t)g_csr[k + 1] * FOUT) + lane);
        unsigned v2 = *((const unsigned*)(g_h2h + (size_t)g_csr[k + 2] * FOUT) + lane);
        unsigned v3 = *((const unsigned*)(g_h2h + (size_t)g_csr[k + 3] * FOUT) + lane);
        float2 f0 = __half22float2(*(__half2*)&v0);
        float2 f1 = __half22float2(*(__half2*)&v1);
        float2 f2 = __half22float2(*(__half2*)&v2);
        float2 f3 = __half22float2(*(__half2*)&v3);
        a0 += (f0.x + f1.x) + (f2.x + f3.x);
        a1 += (f0.y + f1.y) + (f2.y + f3.y);
    }
    for (; k < end; k++) {
        unsigned v = *((const unsigned*)(g_h2h + (size_t)g_csr[k] * FOUT) + lane);
        float2 f = __half22float2(*(__half2*)&v);
        a0 += f.x;
        a1 += f.y;
    }

    float* op = out + (size_t)node * FOUT + 2 * lane;
    op[0] = fmaf(a0, di, b2[2 * lane]);
    op[1] = fmaf(a1, di, b2[2 * lane + 1]);
}

// ---------------------------------------------------------------------------
extern "C" void kernel_launch(void* const* d_in, const int* in_sizes, int n_in,
                              void* d_out, int out_size) {
    const float* x   = (const float*)d_in[0];
    const void*  ei  = d_in[1];
    const float* W1  = (const float*)d_in[2];
    const float* b1  = (const float*)d_in[3];
    const float* W2  = (const float*)d_in[4];
    const float* b2  = (const float*)d_in[5];
    float*       out = (float*)d_out;

    int n = in_sizes[0] / FIN;
    if (n > NMAX) n = NMAX;
    int E = in_sizes[1] / 2;
    if (E > EMAX) E = EMAX;

    int detect_cnt = 2048;
    if (detect_cnt > E) detect_cnt = E;
    int nsb = (n + SCAN_BLK - 1) / SCAN_BLK;

    k_zero_cnt    <<<(n + 255) / 256, 256>>>(n);                 // 1 (also inits g_is64)
    k_detect      <<<(detect_cnt + 255) / 256, 256>>>((const long long*)ei, n, detect_cnt); // 2
    k_convert_hist<<<(E + 255) / 256, 256>>>(ei, E);             // 3
    k_gemm1       <<<(n + 127) / 128, 256>>>(x, W1, n);          // 4 <- profiled
    k_scanA       <<<nsb, SCAN_BLK>>>(n);                        // 5
    k_scanB       <<<1, 256>>>(nsb, n, E);                       // 6
    k_scanC       <<<(n + 255) / 256, 256>>>(n);                 // 7
    k_fill        <<<(E + 255) / 256, 256>>>(E);                 // 8
    k_agg1        <<<(n + 7) / 8, 256>>>(b1, n);                 // 9
    k_gemm2       <<<(n + 127) / 128, 256>>>(W2, n);             // 10
    k_agg2        <<<(n + 7) / 8, 256>>>(out, b2, n);            // 11
}

// round 17
// speedup vs baseline: 1.6221x; 1.0156x over previous
#include <cuda_runtime.h>
#include <cuda_fp16.h>
#include <cstdint>

#define NMAX 100000
#define EMAX 1600000
#define FIN  128
#define FOUT 40
#define SCAN_BLK 1024

typedef unsigned long long ull;

// Scratch (static __device__ — no allocations allowed)
__device__ int    g_is64;
__device__ int    g_src32 [EMAX];
__device__ int    g_dst32 [EMAX];
__device__ int    g_csr   [EMAX];        // src ids grouped by dst
__device__ int    g_degi  [NMAX];
__device__ int    g_fill  [NMAX];
__device__ int    g_rowptr[NMAX + 1];
__device__ int    g_bsum  [(NMAX + SCAN_BLK - 1) / SCAN_BLK];
__device__ int    g_boff  [(NMAX + SCAN_BLK - 1) / SCAN_BLK];
__device__ float  g_dinv[NMAX];
__device__ __half g_hh  [(size_t)NMAX * FIN];   // dinv * (x @ W1), fp16
__device__ __half g_a1h [(size_t)NMAX * FIN];   // relu(layer-1 out), fp16
__device__ __half g_h2h [(size_t)NMAX * FOUT];  // dinv * (a1 @ W2), fp16

// ---------------------------------------------------------------------------
// preproc
// ---------------------------------------------------------------------------
__global__ void k_zero_cnt(int n) {
    int i = blockIdx.x * blockDim.x + threadIdx.x;
    if (i < n) { g_degi[i] = 0; g_fill[i] = 0; }
    if (i == 0) g_is64 = 1;
}

__global__ void k_detect(const long long* __restrict__ ei, int n, int count) {
    int i = blockIdx.x * blockDim.x + threadIdx.x;
    if (i < count) {
        long long v = ei[i];
        if (v < 0 || v >= (long long)n) atomicAnd(&g_is64, 0);
    }
}

__global__ void k_convert_hist(const void* __restrict__ ei, int E) {
    int e = blockIdx.x * blockDim.x + threadIdx.x;
    if (e >= E) return;
    int s, d;
    if (g_is64) {
        const long long* p = (const long long*)ei;
        s = (int)p[e];
        d = (int)p[E + e];
    } else {
        const int* p = (const int*)ei;
        s = p[e];
        d = p[E + e];
    }
    g_src32[e] = s;
    g_dst32[e] = d;
    atomicAdd(&g_degi[d], 1);
}

__global__ void k_scanA(int n) {
    __shared__ int sh[SCAN_BLK];
    int tid = threadIdx.x;
    int i = blockIdx.x * SCAN_BLK + tid;
    int v = (i < n) ? g_degi[i] : 0;
    if (i < n) g_dinv[i] = rsqrtf((float)v + 1.0f);  // +1 = self loop
    sh[tid] = v;
    __syncthreads();
    for (int off = 1; off < SCAN_BLK; off <<= 1) {
        int t = (tid >= off) ? sh[tid - off] : 0;
        __syncthreads();
        sh[tid] += t;
        __syncthreads();
    }
    if (i < n) g_rowptr[i] = sh[tid] - v;  // exclusive within block
    if (tid == SCAN_BLK - 1) g_bsum[blockIdx.x] = sh[tid];
}

__global__ void k_scanB(int nblocks, int n, int E) {
    __shared__ int sh[256];
    int tid = threadIdx.x;
    int carry = 0;
    for (int base = 0; base < nblocks; base += 256) {
        int i = base + tid;
        int v = (i < nblocks) ? g_bsum[i] : 0;
        sh[tid] = v;
        __syncthreads();
        for (int off = 1; off < 256; off <<= 1) {
            int t = (tid >= off) ? sh[tid - off] : 0;
            __syncthreads();
            sh[tid] += t;
            __syncthreads();
        }
        if (i < nblocks) g_boff[i] = carry + sh[tid] - v;
        __syncthreads();
        carry += sh[255];
        __syncthreads();
    }
    if (tid == 0) g_rowptr[n] = E;
}

__global__ void k_scanC(int n) {
    int i = blockIdx.x * blockDim.x + threadIdx.x;
    if (i < n) g_rowptr[i] += g_boff[i / SCAN_BLK];
}

__global__ void k_fill(int E) {
    int e = blockIdx.x * blockDim.x + threadIdx.x;
    if (e >= E) return;
    int d = g_dst32[e];
    int pos = g_rowptr[d] + atomicAdd(&g_fill[d], 1);
    g_csr[pos] = g_src32[e];
}

// ---------------------------------------------------------------------------
// GEMM1 (HMMA): h' = dinv * (x @ W1), fp16 inputs, fp32 acc, fp16 output.
// Core identical to R15-measured-best; epilogue scales by dinv.
// ---------------------------------------------------------------------------
__global__ void __launch_bounds__(256, 2)
k_gemm1(const float* __restrict__ x, const float* __restrict__ W, int n) {
    const int KC = 64;
    __shared__ __half Xs [128 * KC];   // 16 KB, [m][k] swizzled
    __shared__ __half Wsm[KC * FIN];   // 16 KB, [k][n] swizzled

    int t    = threadIdx.x;
    int lane = t & 31;
    int w    = t >> 5;
    int row0 = blockIdx.x * 128;

    unsigned xs_base = (unsigned)__cvta_generic_to_shared(Xs);
    unsigned ws_base = (unsigned)__cvta_generic_to_shared(Wsm);

    float acc[16][4];
#pragma unroll
    for (int nt = 0; nt < 16; nt++)
#pragma unroll
        for (int j = 0; j < 4; j++) acc[nt][j] = 0.f;

    for (int kc = 0; kc < FIN; kc += KC) {
        for (int i = t; i < 128 * KC / 4; i += 256) {
            int r  = i >> 4;
            int c4 = i & 15;
            int gr = row0 + r;
            float4 v = make_float4(0.f, 0.f, 0.f, 0.f);
            if (gr < n) v = ((const float4*)(x + (size_t)gr * FIN + kc))[c4];
            __half2 h01 = __floats2half2_rn(v.x, v.y);
            __half2 h23 = __floats2half2_rn(v.z, v.w);
            unsigned off = (r * (KC * 2) + c4 * 8) ^ ((r & 7) << 4);
            uint2 st;
            st.x = *(unsigned*)&h01;
            st.y = *(unsigned*)&h23;
            *(uint2*)((char*)Xs + off) = st;
        }
        for (int i = t; i < KC * FIN / 4; i += 256) {
            int r  = i >> 5;
            int c4 = i & 31;
            float4 v = ((const float4*)(W + (size_t)(kc + r) * FIN))[c4];
            __half2 h01 = __floats2half2_rn(v.x, v.y);
            __half2 h23 = __floats2half2_rn(v.z, v.w);
            unsigned off = (r * (FIN * 2) + c4 * 8) ^ ((r & 7) << 4);
            uint2 st;
            st.x = *(unsigned*)&h01;
            st.y = *(unsigned*)&h23;
            *(uint2*)((char*)Wsm + off) = st;
        }
        __syncthreads();

#pragma unroll
        for (int kk = 0; kk < KC / 16; kk++) {
            unsigned a0, a1, a2, a3;
            {
                int ar = 16 * w + (lane & 15);
                unsigned off = (ar * (KC * 2) + kk * 32 + ((lane >> 4) << 4))
                               ^ ((ar & 7) << 4);
                asm volatile(
                    "ldmatrix.sync.aligned.m8n8.x4.shared.b16 {%0,%1,%2,%3}, [%4];"
                    : "=r"(a0), "=r"(a1), "=r"(a2), "=r"(a3)
                    : "r"(xs_base + off));
            }
#pragma unroll
            for (int np = 0; np < 8; np++) {
                unsigned b0, b1, b2, b3;
                {
                    int br = kk * 16 + (lane & 15);
                    int ntc = np * 2 + (lane >> 4);
                    unsigned off = (br * (FIN * 2) + ntc * 16) ^ ((br & 7) << 4);
                    asm volatile(
                        "ldmatrix.sync.aligned.m8n8.x4.trans.shared.b16 {%0,%1,%2,%3}, [%4];"
                        : "=r"(b0), "=r"(b1), "=r"(b2), "=r"(b3)
                        : "r"(ws_base + off));
                }
                float* d0 = acc[np * 2];
                float* d1 = acc[np * 2 + 1];
                asm volatile(
                    "mma.sync.aligned.m16n8k16.row.col.f32.f16.f16.f32 "
                    "{%0,%1,%2,%3}, {%4,%5,%6,%7}, {%8,%9}, {%0,%1,%2,%3};"
                    : "+f"(d0[0]), "+f"(d0[1]), "+f"(d0[2]), "+f"(d0[3])
                    : "r"(a0), "r"(a1), "r"(a2), "r"(a3), "r"(b0), "r"(b1));
                asm volatile(
                    "mma.sync.aligned.m16n8k16.row.col.f32.f16.f16.f32 "
                    "{%0,%1,%2,%3}, {%4,%5,%6,%7}, {%8,%9}, {%0,%1,%2,%3};"
                    : "+f"(d1[0]), "+f"(d1[1]), "+f"(d1[2]), "+f"(d1[3])
                    : "r"(a0), "r"(a1), "r"(a2), "r"(a3), "r"(b2), "r"(b3));
            }
        }
        __syncthreads();
    }

    {
        int rlo = row0 + 16 * w + (lane >> 2);
        int rhi = rlo + 8;
        int cbase = (lane & 3) * 2;
        float dlo = (rlo < n) ? g_dinv[rlo] : 0.f;
        float dhi = (rhi < n) ? g_dinv[rhi] : 0.f;
#pragma unroll
        for (int nt = 0; nt < 16; nt++) {
            int col = nt * 8 + cbase;
            if (rlo < n) {
                __half2 p = __floats2half2_rn(acc[nt][0] * dlo, acc[nt][1] * dlo);
                *(unsigned*)(g_hh + (size_t)rlo * FIN + col) = *(unsigned*)&p;
            }
            if (rhi < n) {
                __half2 p = __floats2half2_rn(acc[nt][2] * dhi, acc[nt][3] * dhi);
                *(unsigned*)(g_hh + (size_t)rhi * FIN + col) = *(unsigned*)&p;
            }
        }
    }
}

// ---------------------------------------------------------------------------
// agg1 (pull): a1[d] = relu( di * (sum_s h'[s] + h'[d]) + b1 )   [h' pre-scaled]
// warp per node, lane holds 4 cols; fp16 gathers, plain adds, fp16 store
// ---------------------------------------------------------------------------
__device__ __forceinline__ float4 ld_h4(const __half* p, int lane) {
    uint2 u = *((const uint2*)p + lane);
    float2 lo = __half22float2(*(__half2*)&u.x);
    float2 hi = __half22float2(*(__half2*)&u.y);
    return make_float4(lo.x, lo.y, hi.x, hi.y);
}

__global__ void k_agg1(const float* __restrict__ b1, int n) {
    int node = blockIdx.x * 8 + (threadIdx.x >> 5);
    int lane = threadIdx.x & 31;
    if (node >= n) return;

    float di = g_dinv[node];
    float4 acc = ld_h4(g_hh + (size_t)node * FIN, lane);   // self = h'[d]

    int beg = g_rowptr[node], end = g_rowptr[node + 1];
    int k = beg;
    for (; k + 3 < end; k += 4) {
        int s0 = g_csr[k],     s1 = g_csr[k + 1];
        int s2 = g_csr[k + 2], s3 = g_csr[k + 3];
        float4 v0 = ld_h4(g_hh + (size_t)s0 * FIN, lane);
        float4 v1 = ld_h4(g_hh + (size_t)s1 * FIN, lane);
        float4 v2 = ld_h4(g_hh + (size_t)s2 * FIN, lane);
        float4 v3 = ld_h4(g_hh + (size_t)s3 * FIN, lane);
        acc.x += (v0.x + v1.x) + (v2.x + v3.x);
        acc.y += (v0.y + v1.y) + (v2.y + v3.y);
        acc.z += (v0.z + v1.z) + (v2.z + v3.z);
        acc.w += (v0.w + v1.w) + (v2.w + v3.w);
    }
    for (; k < end; k++) {
        int s = g_csr[k];
        float4 v = ld_h4(g_hh + (size_t)s * FIN, lane);
        acc.x += v.x; acc.y += v.y; acc.z += v.z; acc.w += v.w;
    }

    float4 bb = ((const float4*)b1)[lane];
    float zx = fmaxf(fmaf(acc.x, di, bb.x), 0.f);
    float zy = fmaxf(fmaf(acc.y, di, bb.y), 0.f);
    float zz = fmaxf(fmaf(acc.z, di, bb.z), 0.f);
    float zw = fmaxf(fmaf(acc.w, di, bb.w), 0.f);
    __half2 lo = __floats2half2_rn(zx, zy);
    __half2 hi = __floats2half2_rn(zz, zw);
    uint2 st;
    st.x = *(unsigned*)&lo;
    st.y = *(unsigned*)&hi;
    *((uint2*)(g_a1h + (size_t)node * FIN) + lane) = st;
}

// ---------------------------------------------------------------------------
// GEMM2 (HMMA): h2 = dinv * (a1 @ W2), fp16 in/out, fp32 accumulate.
// EXACT R16 configuration — do not modify.
// ---------------------------------------------------------------------------
__global__ void k_gemm2(const float* __restrict__ W2, int n) {
    __shared__ __half As [128 * 128];  // 32 KB
    __shared__ __half Ws2[128 * 64];   // 16 KB

    int t    = threadIdx.x;
    int lane = t & 31;
    int w    = t >> 5;
    int row0 = blockIdx.x * 128;

    unsigned as_base = (unsigned)__cvta_generic_to_shared(As);
    unsigned ws_base = (unsigned)__cvta_generic_to_shared(Ws2);

    for (int i = t; i < 128 * 16; i += 256) {
        int r = i >> 4;
        int c = i & 15;
        int gr = row0 + r;
        uint4 v = make_uint4(0u, 0u, 0u, 0u);
        if (gr < n) v = *(const uint4*)(g_a1h + (size_t)gr * FIN + c * 8);
        unsigned off = (r * 256 + ((c * 16) ^ ((r & 7) << 4)));
        *(uint4*)((char*)As + off) = v;
    }
    for (int i = t; i < 128 * 8; i += 256) {
        int r = i >> 3;
        int c = i & 7;
        uint4 st = make_uint4(0u, 0u, 0u, 0u);
        if (c < 5) {
            const float4* src = (const float4*)(W2 + (size_t)r * FOUT + c * 8);
            float4 v0 = src[0];
            float4 v1 = src[1];
            __half2 h0 = __floats2half2_rn(v0.x, v0.y);
            __half2 h1 = __floats2half2_rn(v0.z, v0.w);
            __half2 h2 = __floats2half2_rn(v1.x, v1.y);
            __half2 h3 = __floats2half2_rn(v1.z, v1.w);
            st.x = *(unsigned*)&h0; st.y = *(unsigned*)&h1;
            st.z = *(unsigned*)&h2; st.w = *(unsigned*)&h3;
        }
        unsigned off = (r * 128 + ((c * 16) ^ ((r & 7) << 4)));
        *(uint4*)((char*)Ws2 + off) = st;
    }
    __syncthreads();

    float acc[6][4];
#pragma unroll
    for (int nt = 0; nt < 6; nt++)
#pragma unroll
        for (int j = 0; j < 4; j++) acc[nt][j] = 0.f;

#pragma unroll
    for (int kk = 0; kk < 8; kk++) {
        unsigned a0, a1, a2, a3;
        {
            int ar = 16 * w + (lane & 15);
            unsigned off = (ar * 256 + ((kk * 32 + ((lane >> 4) << 4))
                           ^ ((ar & 7) << 4)));
            asm volatile(
                "ldmatrix.sync.aligned.m8n8.x4.shared.b16 {%0,%1,%2,%3}, [%4];"
                : "=r"(a0), "=r"(a1), "=r"(a2), "=r"(a3)
                : "r"(as_base + off));
        }
#pragma unroll
        for (int np = 0; np < 3; np++) {
            unsigned b0, b1, b2, b3;
            {
                int br = kk * 16 + (lane & 15);
                int ntc = np * 2 + (lane >> 4);
                unsigned off = (br * 128 + ((ntc * 16) ^ ((br & 7) << 4)));
                asm volatile(
                    "ldmatrix.sync.aligned.m8n8.x4.trans.shared.b16 {%0,%1,%2,%3}, [%4];"
                    : "=r"(b0), "=r"(b1), "=r"(b2), "=r"(b3)
                    : "r"(ws_base + off));
            }
            float* d0 = acc[np * 2];
            float* d1 = acc[np * 2 + 1];
            asm volatile(
                "mma.sync.aligned.m16n8k16.row.col.f32.f16.f16.f32 "
                "{%0,%1,%2,%3}, {%4,%5,%6,%7}, {%8,%9}, {%0,%1,%2,%3};"
                : "+f"(d0[0]), "+f"(d0[1]), "+f"(d0[2]), "+f"(d0[3])
                : "r"(a0), "r"(a1), "r"(a2), "r"(a3), "r"(b0), "r"(b1));
            asm volatile(
                "mma.sync.aligned.m16n8k16.row.col.f32.f16.f16.f32 "
                "{%0,%1,%2,%3}, {%4,%5,%6,%7}, {%8,%9}, {%0,%1,%2,%3};"
                : "+f"(d1[0]), "+f"(d1[1]), "+f"(d1[2]), "+f"(d1[3])
                : "r"(a0), "r"(a1), "r"(a2), "r"(a3), "r"(b2), "r"(b3));
        }
    }

    {
        int rlo = row0 + 16 * w + (lane >> 2);
        int rhi = rlo + 8;
        int cbase = (lane & 3) * 2;
        float dlo = (rlo < n) ? g_dinv[rlo] : 0.f;
        float dhi = (rhi < n) ? g_dinv[rhi] : 0.f;
#pragma unroll
        for (int nt = 0; nt < 5; nt++) {
            int col = nt * 8 + cbase;
            if (rlo < n) {
                __half2 p = __floats2half2_rn(acc[nt][0] * dlo, acc[nt][1] * dlo);
                *(unsigned*)(g_h2h + (size_t)rlo * FOUT + col) = *(unsigned*)&p;
            }
            if (rhi < n) {
                __half2 p = __floats2half2_rn(acc[nt][2] * dhi, acc[nt][3] * dhi);
                *(unsigned*)(g_h2h + (size_t)rhi * FOUT + col) = *(unsigned*)&p;
            }
        }
    }
}

// ---------------------------------------------------------------------------
// agg2 (pull): out[d] = di * (sum h2[s] + h2[d]) + b2    [h2 pre-scaled fp16]
// ---------------------------------------------------------------------------
__global__ void k_agg2(float* __restrict__ out, const float* __restrict__ b2,
                       int n) {
    int node = blockIdx.x * 8 + (threadIdx.x >> 5);
    int lane = threadIdx.x & 31;
    if (node >= n || lane >= 20) return;

    float di = g_dinv[node];
    unsigned u0 = *((const unsigned*)(g_h2h + (size_t)node * FOUT) + lane);
    float2 sv = __half22float2(*(__half2*)&u0);
    float a0 = sv.x, a1 = sv.y;

    int beg = g_rowptr[node], end = g_rowptr[node + 1];
    int k = beg;
    for (; k + 3 < end; k += 4) {
        unsigned v0 = *((const unsigned*)(g_h2h + (size_t)g_csr[k]     * FOUT) + lane);
        unsigned v1 = *((const unsigned*)(g_h2h + (size_t)g_csr[k + 1] * FOUT) + lane);
        unsigned v2 = *((const unsigned*)(g_h2h + (size_t)g_csr[k + 2] * FOUT) + lane);
        unsigned v3 = *((const unsigned*)(g_h2h + (size_t)g_csr[k + 3] * FOUT) + lane);
        float2 f0 = __half22float2(*(__half2*)&v0);
        float2 f1 = __half22float2(*(__half2*)&v1);
        float2 f2 = __half22float2(*(__half2*)&v2);
        float2 f3 = __half22float2(*(__half2*)&v3);
        a0 += (f0.x + f1.x) + (f2.x + f3.x);
        a1 += (f0.y + f1.y) + (f2.y + f3.y);
    }
    for (; k < end; k++) {
        unsigned v = *((const unsigned*)(g_h2h + (size_t)g_csr[k] * FOUT) + lane);
        float2 f = __half22float2(*(__half2*)&v);
        a0 += f.x;
        a1 += f.y;
    }

    float* op = out + (size_t)node * FOUT + 2 * lane;
    op[0] = fmaf(a0, di, b2[2 * lane]);
    op[1] = fmaf(a1, di, b2[2 * lane + 1]);
}

// ---------------------------------------------------------------------------
extern "C" void kernel_launch(void* const* d_in, const int* in_sizes, int n_in,
                              void* d_out, int out_size) {
    const float* x   = (const float*)d_in[0];
    const void*  ei  = d_in[1];
    const float* W1  = (const float*)d_in[2];
    const float* b1  = (const float*)d_in[3];
    const float* W2  = (const float*)d_in[4];
    const float* b2  = (const float*)d_in[5];
    float*       out = (float*)d_out;

    int n = in_sizes[0] / FIN;
    if (n > NMAX) n = NMAX;
    int E = in_sizes[1] / 2;
    if (E > EMAX) E = EMAX;

    int detect_cnt = 2048;
    if (detect_cnt > E) detect_cnt = E;
    int nsb = (n + SCAN_BLK - 1) / SCAN_BLK;

    k_zero_cnt    <<<(n + 255) / 256, 256>>>(n);                 // 1 (also inits g_is64)
    k_detect      <<<(detect_cnt + 255) / 256, 256>>>((const long long*)ei, n, detect_cnt); // 2
    k_convert_hist<<<(E + 255) / 256, 256>>>(ei, E);             // 3
    k_scanA       <<<nsb, SCAN_BLK>>>(n);                        // 4 <- profiled (computes dinv)
    k_gemm1       <<<(n + 127) / 128, 256>>>(x, W1, n);          // 5 (needs dinv)
    k_scanB       <<<1, 256>>>(nsb, n, E);                       // 6
    k_scanC       <<<(n + 255) / 256, 256>>>(n);                 // 7
    k_fill        <<<(E + 255) / 256, 256>>>(E);                 // 8
    k_agg1        <<<(n + 7) / 8, 256>>>(b1, n);                 // 9
    k_gemm2       <<<(n + 127) / 128, 256>>>(W2, n);             // 10
    k_agg2        <<<(n + 7) / 8, 256>>>(out, b2, n);            // 11
}